// round 2
// baseline (speedup 1.0000x reference)
#include <cuda_runtime.h>
#include <math.h>

// Problem constants (fixed by the dataset)
#define N_NODES   50000
#define N_EDGES   800000
#define N_GRAPHS  64
#define F         256      // F_IN == F_HID
#define F_OUT_    128
#define NF        (N_NODES * F)   // 12,800,000

// ---------------- scratch (device globals; no allocs allowed) ----------------
__device__ float    g_buf0[NF];          // h_lin (x@W1, later h1@W2)
__device__ float    g_buf1[NF];          // agg buffer / h1
__device__ float    g_dinv[N_NODES];     // deg -> rsqrt(deg)
__device__ float    g_cnt[N_GRAPHS];     // nodes per graph
__device__ float    g_psum[N_GRAPHS * F];
__device__ unsigned g_pmax[N_GRAPHS * F]; // float bits; valid order since vals >= 0

// ---------------- init / zero ----------------
__global__ void k_init_small() {
    int i = blockIdx.x * blockDim.x + threadIdx.x;
    int stride = gridDim.x * blockDim.x;
    for (int j = i; j < N_NODES; j += stride) g_dinv[j] = 1.0f;   // self-loop in degree
    for (int j = i; j < N_GRAPHS * F; j += stride) { g_psum[j] = 0.0f; g_pmax[j] = 0u; }
    for (int j = i; j < N_GRAPHS; j += stride) g_cnt[j] = 0.0f;
}

__global__ void k_zero_buf1() {
    int i = blockIdx.x * blockDim.x + threadIdx.x;
    int stride = gridDim.x * blockDim.x;
    float4* p = (float4*)g_buf1;
    const int n4 = NF / 4;
    for (int j = i; j < n4; j += stride) p[j] = make_float4(0.f, 0.f, 0.f, 0.f);
}

// ---------------- degree / norm ----------------
__global__ void k_deg(const int* __restrict__ dst) {
    int e = blockIdx.x * blockDim.x + threadIdx.x;
    if (e < N_EDGES) atomicAdd(&g_dinv[dst[e]], 1.0f);
}

__global__ void k_dinv(const int* __restrict__ batch) {
    int i = blockIdx.x * blockDim.x + threadIdx.x;
    if (i < N_NODES) {
        g_dinv[i] = rsqrtf(g_dinv[i]);             // deg >= 1 always (self loop)
        atomicAdd(&g_cnt[batch[i]], 1.0f);
    }
}

// ---------------- SGEMM: C[M,256] = A[M,256] @ B[256,256], fp32 ----------------
#define BM 128
#define BN 128
#define BK 16

__global__ __launch_bounds__(256) void k_sgemm(const float* __restrict__ A,
                                               const float* __restrict__ B,
                                               float* __restrict__ C, int M) {
    __shared__ float As[BK][BM + 4];
    __shared__ float Bs[BK][BN];
    const int tid  = threadIdx.x;           // 256 threads
    const int bm   = blockIdx.y * BM;
    const int bn   = blockIdx.x * BN;
    const int trow = tid >> 4;              // 0..15
    const int tcol = tid & 15;              // 0..15
    const int tr   = trow * 4;              // A sub-rows: tr.., 64+tr..
    const int tc   = tcol * 4;              // B sub-cols: tc.., 64+tc..

    float acc[8][8];
#pragma unroll
    for (int i = 0; i < 8; i++)
#pragma unroll
        for (int j = 0; j < 8; j++) acc[i][j] = 0.f;

    for (int kk = 0; kk < 256; kk += BK) {
        // A tile: [BM x BK] -> stored transposed As[k][m]
#pragma unroll
        for (int i = 0; i < 2; i++) {
            int idx = i * 256 + tid;        // 0..511 float4 slots
            int ar  = idx >> 2;             // 0..127
            int ac  = (idx & 3) * 4;        // 0,4,8,12
            int grow = bm + ar;
            float4 v = make_float4(0.f, 0.f, 0.f, 0.f);
            if (grow < M) v = *(const float4*)(A + (size_t)grow * 256 + kk + ac);
            As[ac + 0][ar] = v.x; As[ac + 1][ar] = v.y;
            As[ac + 2][ar] = v.z; As[ac + 3][ar] = v.w;
        }
        // B tile: [BK x BN]
#pragma unroll
        for (int i = 0; i < 2; i++) {
            int idx = i * 256 + tid;
            int br  = idx >> 5;              // 0..15
            int bc  = (idx & 31) * 4;        // 0..124
            float4 v = *(const float4*)(B + (size_t)(kk + br) * 256 + bn + bc);
            *(float4*)&Bs[br][bc] = v;
        }
        __syncthreads();

#pragma unroll
        for (int k = 0; k < BK; k++) {
            float4 a0 = *(const float4*)&As[k][tr];
            float4 a1 = *(const float4*)&As[k][64 + tr];
            float4 b0 = *(const float4*)&Bs[k][tc];
            float4 b1 = *(const float4*)&Bs[k][64 + tc];
            float ra[8] = {a0.x, a0.y, a0.z, a0.w, a1.x, a1.y, a1.z, a1.w};
            float rb[8] = {b0.x, b0.y, b0.z, b0.w, b1.x, b1.y, b1.z, b1.w};
#pragma unroll
            for (int i = 0; i < 8; i++)
#pragma unroll
                for (int j = 0; j < 8; j++)
                    acc[i][j] = fmaf(ra[i], rb[j], acc[i][j]);
        }
        __syncthreads();
    }

    // store
#pragma unroll
    for (int ih = 0; ih < 2; ih++) {
#pragma unroll
        for (int ii = 0; ii < 4; ii++) {
            int grow = bm + ih * 64 + tr + ii;
            if (grow < M) {
                float* c = C + (size_t)grow * 256 + bn;
                int i = ih * 4 + ii;
                *(float4*)(c + tc)      = make_float4(acc[i][0], acc[i][1], acc[i][2], acc[i][3]);
                *(float4*)(c + 64 + tc) = make_float4(acc[i][4], acc[i][5], acc[i][6], acc[i][7]);
            }
        }
    }
}

// ---------------- edge scatter: AGG[dst] += H[src] * dinv[src]*dinv[dst] ----------------
__global__ __launch_bounds__(256) void k_scatter(const int* __restrict__ src,
                                                 const int* __restrict__ dst,
                                                 const float* __restrict__ H,
                                                 float* __restrict__ AGG) {
    int e  = blockIdx.x * 4 + (threadIdx.x >> 6);
    int f4 = threadIdx.x & 63;              // 64 float4 = 256 features
    if (e >= N_EDGES) return;
    int s = src[e], d = dst[e];
    float norm = g_dinv[s] * g_dinv[d];
    float4 v = ((const float4*)(H + (size_t)s * F))[f4];
    float* a = AGG + (size_t)d * F + f4 * 4;
    atomicAdd(a + 0, v.x * norm);
    atomicAdd(a + 1, v.y * norm);
    atomicAdd(a + 2, v.z * norm);
    atomicAdd(a + 3, v.w * norm);
}

// ---------------- layer-1 finish: self-loop + bias + relu (in place into AGG) ----------------
__global__ __launch_bounds__(256) void k_biasrelu(float* __restrict__ AGG,
                                                  const float* __restrict__ HL,
                                                  const float* __restrict__ b) {
    int n = blockIdx.x;
    int f = threadIdx.x;
    float di = g_dinv[n];
    size_t idx = (size_t)n * F + f;
    float v = AGG[idx] + HL[idx] * di * di + b[f];
    AGG[idx] = fmaxf(v, 0.f);
}

// ---------------- layer-2 finish + pooling (batch is sorted -> per-block pre-reduce) ----------
#define NPB 128  // nodes per block
__global__ __launch_bounds__(256) void k_finish2(const float* __restrict__ AGG,
                                                 const float* __restrict__ HL,
                                                 const float* __restrict__ b2,
                                                 const int* __restrict__ batch) {
    int f  = threadIdx.x;                   // 0..255
    int n0 = blockIdx.x * NPB;
    int n1 = min(n0 + NPB, N_NODES);
    float bias = b2[f];
    int cur_g = batch[n0];
    float s = 0.f, m = 0.f;
    for (int n = n0; n < n1; ++n) {
        int g = batch[n];                   // uniform across block
        if (g != cur_g) {
            atomicAdd(&g_psum[cur_g * F + f], s);
            atomicMax(&g_pmax[cur_g * F + f], __float_as_uint(m));
            s = 0.f; m = 0.f; cur_g = g;
        }
        float di = g_dinv[n];
        size_t idx = (size_t)n * F + f;
        float v = AGG[idx] + HL[idx] * di * di + bias;
        v = fmaxf(v, 0.f);
        s += v;
        m = fmaxf(m, v);
    }
    atomicAdd(&g_psum[cur_g * F + f], s);
    atomicMax(&g_pmax[cur_g * F + f], __float_as_uint(m));
}

// ---------------- final FC: out[64,128] = [mean|max|sum] @ Wfc + bfc ----------------
__global__ __launch_bounds__(128) void k_fc(const float* __restrict__ Wfc,
                                            const float* __restrict__ bfc,
                                            float* __restrict__ out) {
    int g = blockIdx.x;
    int j = threadIdx.x;                    // 0..127
    float cinv = 1.f / fmaxf(g_cnt[g], 1.f);
    float acc = bfc[j];
#pragma unroll 4
    for (int k = 0; k < F; k++)
        acc = fmaf(g_psum[g * F + k] * cinv, Wfc[(size_t)k * F_OUT_ + j], acc);
#pragma unroll 4
    for (int k = 0; k < F; k++)
        acc = fmaf(__uint_as_float(g_pmax[g * F + k]), Wfc[(size_t)(F + k) * F_OUT_ + j], acc);
#pragma unroll 4
    for (int k = 0; k < F; k++)
        acc = fmaf(g_psum[g * F + k], Wfc[(size_t)(2 * F + k) * F_OUT_ + j], acc);
    out[(size_t)g * F_OUT_ + j] = acc;
}

// ---------------- launcher ----------------
extern "C" void kernel_launch(void* const* d_in, const int* in_sizes, int n_in,
                              void* d_out, int out_size) {
    const float* x     = (const float*)d_in[0];
    const int*   ei    = (const int*)d_in[1];
    const int*   batch = (const int*)d_in[2];
    // trailing 6 arrays are W1,b1,W2,b2,Wfc,bfc regardless of whether n_graphs
    // appears as a scalar input
    int w = n_in - 6;
    const float* W1  = (const float*)d_in[w + 0];
    const float* b1  = (const float*)d_in[w + 1];
    const float* W2  = (const float*)d_in[w + 2];
    const float* b2  = (const float*)d_in[w + 3];
    const float* Wfc = (const float*)d_in[w + 4];
    const float* bfc = (const float*)d_in[w + 5];
    float* out = (float*)d_out;

    const int* src = ei;
    const int* dst = ei + N_EDGES;

    float* buf0; cudaGetSymbolAddress((void**)&buf0, g_buf0);
    float* buf1; cudaGetSymbolAddress((void**)&buf1, g_buf1);

    dim3 ggrid(256 / BN * 1 + 1, (N_NODES + BM - 1) / BM);  // (2, 391)
    ggrid.x = 256 / BN;                                     // exactly 2

    k_init_small<<<256, 256>>>();
    k_zero_buf1<<<4096, 256>>>();
    k_deg<<<(N_EDGES + 255) / 256, 256>>>(dst);
    k_dinv<<<(N_NODES + 255) / 256, 256>>>(batch);

    // layer 1
    k_sgemm<<<ggrid, 256>>>(x, W1, buf0, N_NODES);
    k_scatter<<<(N_EDGES + 3) / 4, 256>>>(src, dst, buf0, buf1);
    k_biasrelu<<<N_NODES, 256>>>(buf1, buf0, b1);           // buf1 := h1

    // layer 2
    k_sgemm<<<ggrid, 256>>>(buf1, W2, buf0, N_NODES);       // buf0 := h1 @ W2
    k_zero_buf1<<<4096, 256>>>();
    k_scatter<<<(N_EDGES + 3) / 4, 256>>>(src, dst, buf0, buf1);
    k_finish2<<<(N_NODES + NPB - 1) / NPB, 256>>>(buf1, buf0, b2, batch);

    // readout
    k_fc<<<N_GRAPHS, 128>>>(Wfc, bfc, out);
    (void)in_sizes; (void)out_size;
}

// round 5
// speedup vs baseline: 1.0552x; 1.0552x over previous
#include <cuda_runtime.h>
#include <cuda_bf16.h>
#include <math.h>
#include <stdint.h>

// Problem constants (fixed by the dataset)
#define N_NODES   50000
#define N_EDGES   800000
#define N_GRAPHS  64
#define F         256      // F_IN == F_HID
#define F_OUT_    128
#define NF        (N_NODES * F)   // 12,800,000

// ---------------- scratch (device globals; no allocs allowed) ----------------
__device__ float    g_buf0[NF];          // h_lin (x@W1, later h1@W2)
__device__ float    g_buf1[NF];          // agg buffer / h1
__device__ float    g_dinv[N_NODES];     // deg -> rsqrt(deg)
__device__ float    g_cnt[N_GRAPHS];     // nodes per graph
__device__ float    g_psum[N_GRAPHS * F];
__device__ unsigned g_pmax[N_GRAPHS * F]; // float bits; valid order since vals >= 0

// bf16-split weights (hi/lo) for both layers
__device__ __nv_bfloat16 g_B1h[F * F], g_B1l[F * F];
__device__ __nv_bfloat16 g_B2h[F * F], g_B2l[F * F];

// ---------------- init / zero ----------------
__global__ void k_init_small() {
    int i = blockIdx.x * blockDim.x + threadIdx.x;
    int stride = gridDim.x * blockDim.x;
    for (int j = i; j < N_NODES; j += stride) g_dinv[j] = 1.0f;   // self-loop in degree
    for (int j = i; j < N_GRAPHS * F; j += stride) { g_psum[j] = 0.0f; g_pmax[j] = 0u; }
    for (int j = i; j < N_GRAPHS; j += stride) g_cnt[j] = 0.0f;
}

__global__ void k_zero_buf1() {
    int i = blockIdx.x * blockDim.x + threadIdx.x;
    int stride = gridDim.x * blockDim.x;
    float4* p = (float4*)g_buf1;
    const int n4 = NF / 4;
    for (int j = i; j < n4; j += stride) p[j] = make_float4(0.f, 0.f, 0.f, 0.f);
}

// ---------------- degree / norm ----------------
__global__ void k_deg(const int* __restrict__ dst) {
    int e = blockIdx.x * blockDim.x + threadIdx.x;
    if (e < N_EDGES) atomicAdd(&g_dinv[dst[e]], 1.0f);
}

__global__ void k_dinv(const int* __restrict__ batch) {
    int i = blockIdx.x * blockDim.x + threadIdx.x;
    if (i < N_NODES) {
        g_dinv[i] = rsqrtf(g_dinv[i]);             // deg >= 1 always (self loop)
        atomicAdd(&g_cnt[batch[i]], 1.0f);
    }
}

// ---------------- weight split: W -> bf16 hi/lo ----------------
__global__ void k_convB(const float* __restrict__ W,
                        __nv_bfloat16* __restrict__ Bh,
                        __nv_bfloat16* __restrict__ Bl) {
    int i = blockIdx.x * blockDim.x + threadIdx.x;
    if (i < F * F) {
        float v = W[i];
        __nv_bfloat16 h = __float2bfloat16(v);
        Bh[i] = h;
        Bl[i] = __float2bfloat16(v - __bfloat162float(h));
    }
}

// ---------------- tensor-core GEMM: C[M,256] = A[M,256] @ W[256,256] ----------
// bf16 split: C ≈ Ahi*Bhi + Ahi*Blo + Alo*Bhi (fp32 accumulate)
#define BM 128
#define BN 128
#define KC 32
#define APAD 40    // row pad (bf16 elems) -> 80B rows, conflict-free ldmatrix
#define BPAD 136   // -> 272B rows, conflict-free ldmatrix.trans

__device__ __forceinline__ void ldsm_x4(uint32_t& r0, uint32_t& r1, uint32_t& r2, uint32_t& r3,
                                        uint32_t addr) {
    asm volatile("ldmatrix.sync.aligned.m8n8.x4.shared.b16 {%0,%1,%2,%3}, [%4];\n"
                 : "=r"(r0), "=r"(r1), "=r"(r2), "=r"(r3) : "r"(addr));
}
__device__ __forceinline__ void ldsm_x4t(uint32_t& r0, uint32_t& r1, uint32_t& r2, uint32_t& r3,
                                         uint32_t addr) {
    asm volatile("ldmatrix.sync.aligned.m8n8.x4.trans.shared.b16 {%0,%1,%2,%3}, [%4];\n"
                 : "=r"(r0), "=r"(r1), "=r"(r2), "=r"(r3) : "r"(addr));
}
__device__ __forceinline__ void mma_bf16(float* c, const uint32_t* a, uint32_t b0, uint32_t b1) {
    asm volatile("mma.sync.aligned.m16n8k16.row.col.f32.bf16.bf16.f32 "
                 "{%0,%1,%2,%3}, {%4,%5,%6,%7}, {%8,%9}, {%0,%1,%2,%3};\n"
                 : "+f"(c[0]), "+f"(c[1]), "+f"(c[2]), "+f"(c[3])
                 : "r"(a[0]), "r"(a[1]), "r"(a[2]), "r"(a[3]), "r"(b0), "r"(b1));
}
__device__ __forceinline__ uint32_t pack_bf2(__nv_bfloat16 a, __nv_bfloat16 b) {
    __nv_bfloat162 p = __halves2bfloat162(a, b);
    return *(uint32_t*)&p;
}

__global__ __launch_bounds__(256) void k_gemm_tc(const float* __restrict__ A,
                                                 const __nv_bfloat16* __restrict__ Bh,
                                                 const __nv_bfloat16* __restrict__ Bl,
                                                 float* __restrict__ C, int M) {
    __shared__ __nv_bfloat16 sAh[BM * APAD];
    __shared__ __nv_bfloat16 sAl[BM * APAD];
    __shared__ __nv_bfloat16 sBh[KC * BPAD];
    __shared__ __nv_bfloat16 sBl[KC * BPAD];

    const int tid  = threadIdx.x;
    const int lane = tid & 31;
    const int wid  = tid >> 5;          // 0..7
    const int wm   = wid >> 1;          // 0..3  -> M offset wm*32
    const int wn   = wid & 1;           // 0..1  -> N offset wn*64
    const int bm   = blockIdx.y * BM;
    const int bn   = blockIdx.x * BN;

    // ldmatrix lane addressing: groups of 8 lanes feed one 8x8 matrix
    const int lr = lane & 7;
    const int lg = lane >> 3;
    const int rowoff = ((lg & 1) << 3) + lr;    // +8 for mats 1,3
    const int coloff = (lg & 2) << 2;           // +8 cols for mats 2,3

    float acc[2][8][4];
#pragma unroll
    for (int i = 0; i < 2; i++)
#pragma unroll
        for (int j = 0; j < 8; j++)
#pragma unroll
            for (int k = 0; k < 4; k++) acc[i][j][k] = 0.f;

    for (int kk = 0; kk < 256; kk += KC) {
        // ---- load A tile [BM x KC] fp32, split to bf16 hi/lo in SMEM ----
#pragma unroll
        for (int i = 0; i < 4; i++) {
            int idx = i * 256 + tid;            // 0..1023 float4 slots
            int r = idx >> 3;                   // 0..127
            int c = (idx & 7) * 4;              // 0..28
            int grow = bm + r;
            float4 v = make_float4(0.f, 0.f, 0.f, 0.f);
            if (grow < M) v = *(const float4*)(A + (size_t)grow * 256 + kk + c);
            __nv_bfloat16 h0 = __float2bfloat16(v.x), h1 = __float2bfloat16(v.y);
            __nv_bfloat16 h2 = __float2bfloat16(v.z), h3 = __float2bfloat16(v.w);
            __nv_bfloat16 l0 = __float2bfloat16(v.x - __bfloat162float(h0));
            __nv_bfloat16 l1 = __float2bfloat16(v.y - __bfloat162float(h1));
            __nv_bfloat16 l2 = __float2bfloat16(v.z - __bfloat162float(h2));
            __nv_bfloat16 l3 = __float2bfloat16(v.w - __bfloat162float(h3));
            uint32_t* ph = (uint32_t*)&sAh[r * APAD + c];
            uint32_t* pl = (uint32_t*)&sAl[r * APAD + c];
            ph[0] = pack_bf2(h0, h1); ph[1] = pack_bf2(h2, h3);
            pl[0] = pack_bf2(l0, l1); pl[1] = pack_bf2(l2, l3);
        }
        // ---- load B tile [KC x BN] bf16 (hi & lo) ----
#pragma unroll
        for (int i = 0; i < 2; i++) {
            int idx = i * 256 + tid;            // 0..511 uint4 slots (8 bf16 each)
            int r = idx >> 4;                   // 0..31
            int c = (idx & 15) * 8;             // 0..120
            uint4 vh = *(const uint4*)(Bh + (size_t)(kk + r) * 256 + bn + c);
            uint4 vl = *(const uint4*)(Bl + (size_t)(kk + r) * 256 + bn + c);
            *(uint4*)&sBh[r * BPAD + c] = vh;
            *(uint4*)&sBl[r * BPAD + c] = vl;
        }
        __syncthreads();

#pragma unroll
        for (int kf = 0; kf < KC; kf += 16) {
            uint32_t ah[2][4], al[2][4];
#pragma unroll
            for (int mt = 0; mt < 2; mt++) {
                int rowi = (wm * 32 + mt * 16 + rowoff) * APAD + kf + coloff;
                ldsm_x4(ah[mt][0], ah[mt][1], ah[mt][2], ah[mt][3],
                        (uint32_t)__cvta_generic_to_shared(&sAh[rowi]));
                ldsm_x4(al[mt][0], al[mt][1], al[mt][2], al[mt][3],
                        (uint32_t)__cvta_generic_to_shared(&sAl[rowi]));
            }
            uint32_t bh[4][4], bl[4][4];
#pragma unroll
            for (int nt4 = 0; nt4 < 4; nt4++) {
                int ci = (kf + rowoff) * BPAD + wn * 64 + nt4 * 16 + coloff;
                ldsm_x4t(bh[nt4][0], bh[nt4][1], bh[nt4][2], bh[nt4][3],
                         (uint32_t)__cvta_generic_to_shared(&sBh[ci]));
                ldsm_x4t(bl[nt4][0], bl[nt4][1], bl[nt4][2], bl[nt4][3],
                         (uint32_t)__cvta_generic_to_shared(&sBl[ci]));
            }
#pragma unroll
            for (int mt = 0; mt < 2; mt++) {
#pragma unroll
                for (int nt4 = 0; nt4 < 4; nt4++) {
                    // hi*hi
                    mma_bf16(acc[mt][nt4 * 2 + 0], ah[mt], bh[nt4][0], bh[nt4][1]);
                    mma_bf16(acc[mt][nt4 * 2 + 1], ah[mt], bh[nt4][2], bh[nt4][3]);
                    // hi*lo
                    mma_bf16(acc[mt][nt4 * 2 + 0], ah[mt], bl[nt4][0], bl[nt4][1]);
                    mma_bf16(acc[mt][nt4 * 2 + 1], ah[mt], bl[nt4][2], bl[nt4][3]);
                    // lo*hi
                    mma_bf16(acc[mt][nt4 * 2 + 0], al[mt], bh[nt4][0], bh[nt4][1]);
                    mma_bf16(acc[mt][nt4 * 2 + 1], al[mt], bh[nt4][2], bh[nt4][3]);
                }
            }
        }
        __syncthreads();
    }

    // ---- store C ----
    const int gid2 = lane >> 2;
    const int tig  = lane & 3;
#pragma unroll
    for (int mt = 0; mt < 2; mt++) {
#pragma unroll
        for (int nt = 0; nt < 8; nt++) {
            int row0 = bm + wm * 32 + mt * 16 + gid2;
            int col  = bn + wn * 64 + nt * 8 + tig * 2;
            float* c0 = C + (size_t)row0 * 256 + col;
            if (row0 < M)
                *(float2*)c0 = make_float2(acc[mt][nt][0], acc[mt][nt][1]);
            if (row0 + 8 < M)
                *(float2*)(c0 + 8 * 256) = make_float2(acc[mt][nt][2], acc[mt][nt][3]);
        }
    }
}

// ---------------- edge scatter: AGG[dst] += H[src] * dinv[src]*dinv[dst] ----------------
__global__ __launch_bounds__(256) void k_scatter(const int* __restrict__ src,
                                                 const int* __restrict__ dst,
                                                 const float* __restrict__ H,
                                                 float* __restrict__ AGG) {
    int e  = blockIdx.x * 4 + (threadIdx.x >> 6);
    int f4 = threadIdx.x & 63;              // 64 float4 = 256 features
    if (e >= N_EDGES) return;
    int s = src[e], d = dst[e];
    float norm = g_dinv[s] * g_dinv[d];
    float4 v = ((const float4*)(H + (size_t)s * F))[f4];
    float* a = AGG + (size_t)d * F + f4 * 4;
    atomicAdd(a + 0, v.x * norm);
    atomicAdd(a + 1, v.y * norm);
    atomicAdd(a + 2, v.z * norm);
    atomicAdd(a + 3, v.w * norm);
}

// ---------------- layer-1 finish: self-loop + bias + relu (in place into AGG) ----------------
__global__ __launch_bounds__(256) void k_biasrelu(float* __restrict__ AGG,
                                                  const float* __restrict__ HL,
                                                  const float* __restrict__ b) {
    int n = blockIdx.x;
    int f = threadIdx.x;
    float di = g_dinv[n];
    size_t idx = (size_t)n * F + f;
    float v = AGG[idx] + HL[idx] * di * di + b[f];
    AGG[idx] = fmaxf(v, 0.f);
}

// ---------------- layer-2 finish + pooling (batch sorted -> per-block pre-reduce) ----------
#define NPB 128  // nodes per block
__global__ __launch_bounds__(256) void k_finish2(const float* __restrict__ AGG,
                                                 const float* __restrict__ HL,
                                                 const float* __restrict__ b2,
                                                 const int* __restrict__ batch) {
    int f  = threadIdx.x;                   // 0..255
    int n0 = blockIdx.x * NPB;
    int n1 = min(n0 + NPB, N_NODES);
    float bias = b2[f];
    int cur_g = batch[n0];
    float s = 0.f, m = 0.f;
    for (int n = n0; n < n1; ++n) {
        int g = batch[n];                   // uniform across block
        if (g != cur_g) {
            atomicAdd(&g_psum[cur_g * F + f], s);
            atomicMax(&g_pmax[cur_g * F + f], __float_as_uint(m));
            s = 0.f; m = 0.f; cur_g = g;
        }
        float di = g_dinv[n];
        size_t idx = (size_t)n * F + f;
        float v = AGG[idx] + HL[idx] * di * di + bias;
        v = fmaxf(v, 0.f);
        s += v;
        m = fmaxf(m, v);
    }
    atomicAdd(&g_psum[cur_g * F + f], s);
    atomicMax(&g_pmax[cur_g * F + f], __float_as_uint(m));
}

// ---------------- final FC: out[64,128] = [mean|max|sum] @ Wfc + bfc ----------------
__global__ __launch_bounds__(128) void k_fc(const float* __restrict__ Wfc,
                                            const float* __restrict__ bfc,
                                            float* __restrict__ out) {
    int g = blockIdx.x;
    int j = threadIdx.x;                    // 0..127
    float cinv = 1.f / fmaxf(g_cnt[g], 1.f);
    float acc = bfc[j];
#pragma unroll 4
    for (int k = 0; k < F; k++)
        acc = fmaf(g_psum[g * F + k] * cinv, Wfc[(size_t)k * F_OUT_ + j], acc);
#pragma unroll 4
    for (int k = 0; k < F; k++)
        acc = fmaf(__uint_as_float(g_pmax[g * F + k]), Wfc[(size_t)(F + k) * F_OUT_ + j], acc);
#pragma unroll 4
    for (int k = 0; k < F; k++)
        acc = fmaf(g_psum[g * F + k], Wfc[(size_t)(2 * F + k) * F_OUT_ + j], acc);
    out[(size_t)g * F_OUT_ + j] = acc;
}

// ---------------- launcher ----------------
extern "C" void kernel_launch(void* const* d_in, const int* in_sizes, int n_in,
                              void* d_out, int out_size) {
    const float* x     = (const float*)d_in[0];
    const int*   ei    = (const int*)d_in[1];
    const int*   batch = (const int*)d_in[2];
    int w = n_in - 6;
    const float* W1  = (const float*)d_in[w + 0];
    const float* b1  = (const float*)d_in[w + 1];
    const float* W2  = (const float*)d_in[w + 2];
    const float* b2  = (const float*)d_in[w + 3];
    const float* Wfc = (const float*)d_in[w + 4];
    const float* bfc = (const float*)d_in[w + 5];
    float* out = (float*)d_out;

    const int* src = ei;
    const int* dst = ei + N_EDGES;

    float* buf0; cudaGetSymbolAddress((void**)&buf0, g_buf0);
    float* buf1; cudaGetSymbolAddress((void**)&buf1, g_buf1);
    __nv_bfloat16 *B1h, *B1l, *B2h, *B2l;
    cudaGetSymbolAddress((void**)&B1h, g_B1h);
    cudaGetSymbolAddress((void**)&B1l, g_B1l);
    cudaGetSymbolAddress((void**)&B2h, g_B2h);
    cudaGetSymbolAddress((void**)&B2l, g_B2l);

    dim3 ggrid(2, (N_NODES + BM - 1) / BM);   // (2, 391)

    k_init_small<<<256, 256>>>();
    k_zero_buf1<<<4096, 256>>>();
    k_convB<<<(F * F + 255) / 256, 256>>>(W1, B1h, B1l);
    k_convB<<<(F * F + 255) / 256, 256>>>(W2, B2h, B2l);
    k_deg<<<(N_EDGES + 255) / 256, 256>>>(dst);
    k_dinv<<<(N_NODES + 255) / 256, 256>>>(batch);

    // layer 1
    k_gemm_tc<<<ggrid, 256>>>(x, B1h, B1l, buf0, N_NODES);
    k_scatter<<<(N_EDGES + 3) / 4, 256>>>(src, dst, buf0, buf1);
    k_biasrelu<<<N_NODES, 256>>>(buf1, buf0, b1);           // buf1 := h1

    // layer 2
    k_gemm_tc<<<ggrid, 256>>>(buf1, B2h, B2l, buf0, N_NODES);
    k_zero_buf1<<<4096, 256>>>();
    k_scatter<<<(N_EDGES + 3) / 4, 256>>>(src, dst, buf0, buf1);
    k_finish2<<<(N_NODES + NPB - 1) / NPB, 256>>>(buf1, buf0, b2, batch);

    // readout
    k_fc<<<N_GRAPHS, 128>>>(Wfc, bfc, out);
    (void)in_sizes; (void)out_size;
}

// round 7
// speedup vs baseline: 2.6732x; 2.5335x over previous
#include <cuda_runtime.h>
#include <cuda_bf16.h>
#include <math.h>
#include <stdint.h>

// Problem constants (fixed by the dataset)
#define N_NODES   50000
#define N_EDGES   800000
#define N_GRAPHS  64
#define F         256      // F_IN == F_HID
#define F_OUT_    128
#define NF        (N_NODES * F)   // 12,800,000

// ---------------- scratch (device globals; no allocs allowed) ----------------
__device__ float    g_buf0[NF];          // h_lin (x@W1, later h1@W2)
__device__ float    g_buf1[NF];          // h1 / h2
__device__ float    g_dinv[N_NODES];     // rsqrt(1+deg)
__device__ int      g_degi[N_NODES];     // in-degree (excl self loop)
__device__ int      g_rowstart[N_NODES + 1];
__device__ int      g_cursor[N_NODES];
__device__ int      g_esrc[N_EDGES];     // CSR by dst: src ids
__device__ float    g_enorm[N_EDGES];    // CSR by dst: dinv[src]*dinv[dst]
__device__ float    g_cnt[N_GRAPHS];     // nodes per graph
__device__ float    g_psum[N_GRAPHS * F];
__device__ unsigned g_pmax[N_GRAPHS * F]; // float bits; valid since vals >= 0

// bf16-split weights (hi/lo) for both layers
__device__ __nv_bfloat16 g_B1h[F * F], g_B1l[F * F];
__device__ __nv_bfloat16 g_B2h[F * F], g_B2l[F * F];

// ---------------- init ----------------
__global__ void k_init_small() {
    int i = blockIdx.x * blockDim.x + threadIdx.x;
    int stride = gridDim.x * blockDim.x;
    for (int j = i; j < N_NODES; j += stride) g_degi[j] = 0;
    for (int j = i; j < N_GRAPHS * F; j += stride) { g_psum[j] = 0.0f; g_pmax[j] = 0u; }
    for (int j = i; j < N_GRAPHS; j += stride) g_cnt[j] = 0.0f;
}

// ---------------- degree / norm ----------------
__global__ void k_deg(const int* __restrict__ dst) {
    int e = blockIdx.x * blockDim.x + threadIdx.x;
    if (e < N_EDGES) atomicAdd(&g_degi[dst[e]], 1);
}

__global__ void k_dinv(const int* __restrict__ batch) {
    int i = blockIdx.x * blockDim.x + threadIdx.x;
    if (i < N_NODES) {
        g_dinv[i] = rsqrtf(1.0f + (float)g_degi[i]);   // self loop included
        atomicAdd(&g_cnt[batch[i]], 1.0f);
    }
}

// ---------------- exclusive scan of degrees -> rowstart/cursor (1 block) ----------------
__global__ __launch_bounds__(1024) void k_scan() {
    __shared__ int part[1024];
    int t = threadIdx.x;
    const int CH = (N_NODES + 1023) / 1024;     // 49
    int s0 = t * CH;
    int s1 = min(s0 + CH, N_NODES);
    int sum = 0;
    for (int i = s0; i < s1; i++) sum += g_degi[i];
    part[t] = sum;
    __syncthreads();
    for (int off = 1; off < 1024; off <<= 1) {
        int v = (t >= off) ? part[t - off] : 0;
        __syncthreads();
        part[t] += v;
        __syncthreads();
    }
    int excl = (t == 0) ? 0 : part[t - 1];
    for (int i = s0; i < s1; i++) {
        g_rowstart[i] = excl;
        g_cursor[i] = excl;
        excl += g_degi[i];
    }
    if (t == 1023) g_rowstart[N_NODES] = excl;   // == total (tail chunks empty)
}

// ---------------- CSR fill: place (src, norm) per edge, grouped by dst ----------------
__global__ void k_fill(const int* __restrict__ src, const int* __restrict__ dst) {
    int e = blockIdx.x * blockDim.x + threadIdx.x;
    if (e < N_EDGES) {
        int s = src[e], d = dst[e];
        int pos = atomicAdd(&g_cursor[d], 1);
        g_esrc[pos] = s;
        g_enorm[pos] = g_dinv[s] * g_dinv[d];
    }
}

// ---------------- weight split: W -> bf16 hi/lo ----------------
__global__ void k_convB(const float* __restrict__ W,
                        __nv_bfloat16* __restrict__ Bh,
                        __nv_bfloat16* __restrict__ Bl) {
    int i = blockIdx.x * blockDim.x + threadIdx.x;
    if (i < F * F) {
        float v = W[i];
        __nv_bfloat16 h = __float2bfloat16(v);
        Bh[i] = h;
        Bl[i] = __float2bfloat16(v - __bfloat162float(h));
    }
}

// ---------------- tensor-core GEMM: C[M,256] = A[M,256] @ W[256,256] ----------
// bf16 split: C ≈ Ahi*Bhi + Ahi*Blo + Alo*Bhi (fp32 accumulate)
#define BM 128
#define BN 128
#define KC 32
#define APAD 40
#define BPAD 136

__device__ __forceinline__ void ldsm_x4(uint32_t& r0, uint32_t& r1, uint32_t& r2, uint32_t& r3,
                                        uint32_t addr) {
    asm volatile("ldmatrix.sync.aligned.m8n8.x4.shared.b16 {%0,%1,%2,%3}, [%4];\n"
                 : "=r"(r0), "=r"(r1), "=r"(r2), "=r"(r3) : "r"(addr));
}
__device__ __forceinline__ void ldsm_x4t(uint32_t& r0, uint32_t& r1, uint32_t& r2, uint32_t& r3,
                                         uint32_t addr) {
    asm volatile("ldmatrix.sync.aligned.m8n8.x4.trans.shared.b16 {%0,%1,%2,%3}, [%4];\n"
                 : "=r"(r0), "=r"(r1), "=r"(r2), "=r"(r3) : "r"(addr));
}
__device__ __forceinline__ void mma_bf16(float* c, const uint32_t* a, uint32_t b0, uint32_t b1) {
    asm volatile("mma.sync.aligned.m16n8k16.row.col.f32.bf16.bf16.f32 "
                 "{%0,%1,%2,%3}, {%4,%5,%6,%7}, {%8,%9}, {%0,%1,%2,%3};\n"
                 : "+f"(c[0]), "+f"(c[1]), "+f"(c[2]), "+f"(c[3])
                 : "r"(a[0]), "r"(a[1]), "r"(a[2]), "r"(a[3]), "r"(b0), "r"(b1));
}
__device__ __forceinline__ uint32_t pack_bf2(__nv_bfloat16 a, __nv_bfloat16 b) {
    __nv_bfloat162 p = __halves2bfloat162(a, b);
    return *(uint32_t*)&p;
}

__global__ __launch_bounds__(256) void k_gemm_tc(const float* __restrict__ A,
                                                 const __nv_bfloat16* __restrict__ Bh,
                                                 const __nv_bfloat16* __restrict__ Bl,
                                                 float* __restrict__ C, int M) {
    __shared__ __nv_bfloat16 sAh[BM * APAD];
    __shared__ __nv_bfloat16 sAl[BM * APAD];
    __shared__ __nv_bfloat16 sBh[KC * BPAD];
    __shared__ __nv_bfloat16 sBl[KC * BPAD];

    const int tid  = threadIdx.x;
    const int lane = tid & 31;
    const int wid  = tid >> 5;
    const int wm   = wid >> 1;
    const int wn   = wid & 1;
    const int bm   = blockIdx.y * BM;
    const int bn   = blockIdx.x * BN;

    const int lr = lane & 7;
    const int lg = lane >> 3;
    const int rowoff = ((lg & 1) << 3) + lr;
    const int coloff = (lg & 2) << 2;

    float acc[2][8][4];
#pragma unroll
    for (int i = 0; i < 2; i++)
#pragma unroll
        for (int j = 0; j < 8; j++)
#pragma unroll
            for (int k = 0; k < 4; k++) acc[i][j][k] = 0.f;

    for (int kk = 0; kk < 256; kk += KC) {
#pragma unroll
        for (int i = 0; i < 4; i++) {
            int idx = i * 256 + tid;
            int r = idx >> 3;
            int c = (idx & 7) * 4;
            int grow = bm + r;
            float4 v = make_float4(0.f, 0.f, 0.f, 0.f);
            if (grow < M) v = *(const float4*)(A + (size_t)grow * 256 + kk + c);
            __nv_bfloat16 h0 = __float2bfloat16(v.x), h1 = __float2bfloat16(v.y);
            __nv_bfloat16 h2 = __float2bfloat16(v.z), h3 = __float2bfloat16(v.w);
            __nv_bfloat16 l0 = __float2bfloat16(v.x - __bfloat162float(h0));
            __nv_bfloat16 l1 = __float2bfloat16(v.y - __bfloat162float(h1));
            __nv_bfloat16 l2 = __float2bfloat16(v.z - __bfloat162float(h2));
            __nv_bfloat16 l3 = __float2bfloat16(v.w - __bfloat162float(h3));
            uint32_t* ph = (uint32_t*)&sAh[r * APAD + c];
            uint32_t* pl = (uint32_t*)&sAl[r * APAD + c];
            ph[0] = pack_bf2(h0, h1); ph[1] = pack_bf2(h2, h3);
            pl[0] = pack_bf2(l0, l1); pl[1] = pack_bf2(l2, l3);
        }
#pragma unroll
        for (int i = 0; i < 2; i++) {
            int idx = i * 256 + tid;
            int r = idx >> 4;
            int c = (idx & 15) * 8;
            uint4 vh = *(const uint4*)(Bh + (size_t)(kk + r) * 256 + bn + c);
            uint4 vl = *(const uint4*)(Bl + (size_t)(kk + r) * 256 + bn + c);
            *(uint4*)&sBh[r * BPAD + c] = vh;
            *(uint4*)&sBl[r * BPAD + c] = vl;
        }
        __syncthreads();

#pragma unroll
        for (int kf = 0; kf < KC; kf += 16) {
            uint32_t ah[2][4], al[2][4];
#pragma unroll
            for (int mt = 0; mt < 2; mt++) {
                int rowi = (wm * 32 + mt * 16 + rowoff) * APAD + kf + coloff;
                ldsm_x4(ah[mt][0], ah[mt][1], ah[mt][2], ah[mt][3],
                        (uint32_t)__cvta_generic_to_shared(&sAh[rowi]));
                ldsm_x4(al[mt][0], al[mt][1], al[mt][2], al[mt][3],
                        (uint32_t)__cvta_generic_to_shared(&sAl[rowi]));
            }
            uint32_t bh[4][4], bl[4][4];
#pragma unroll
            for (int nt4 = 0; nt4 < 4; nt4++) {
                int ci = (kf + rowoff) * BPAD + wn * 64 + nt4 * 16 + coloff;
                ldsm_x4t(bh[nt4][0], bh[nt4][1], bh[nt4][2], bh[nt4][3],
                         (uint32_t)__cvta_generic_to_shared(&sBh[ci]));
                ldsm_x4t(bl[nt4][0], bl[nt4][1], bl[nt4][2], bl[nt4][3],
                         (uint32_t)__cvta_generic_to_shared(&sBl[ci]));
            }
#pragma unroll
            for (int mt = 0; mt < 2; mt++) {
#pragma unroll
                for (int nt4 = 0; nt4 < 4; nt4++) {
                    mma_bf16(acc[mt][nt4 * 2 + 0], ah[mt], bh[nt4][0], bh[nt4][1]);
                    mma_bf16(acc[mt][nt4 * 2 + 1], ah[mt], bh[nt4][2], bh[nt4][3]);
                    mma_bf16(acc[mt][nt4 * 2 + 0], ah[mt], bl[nt4][0], bl[nt4][1]);
                    mma_bf16(acc[mt][nt4 * 2 + 1], ah[mt], bl[nt4][2], bl[nt4][3]);
                    mma_bf16(acc[mt][nt4 * 2 + 0], al[mt], bh[nt4][0], bh[nt4][1]);
                    mma_bf16(acc[mt][nt4 * 2 + 1], al[mt], bh[nt4][2], bh[nt4][3]);
                }
            }
        }
        __syncthreads();
    }

    const int gid2 = lane >> 2;
    const int tig  = lane & 3;
#pragma unroll
    for (int mt = 0; mt < 2; mt++) {
#pragma unroll
        for (int nt = 0; nt < 8; nt++) {
            int row0 = bm + wm * 32 + mt * 16 + gid2;
            int col  = bn + wn * 64 + nt * 8 + tig * 2;
            float* c0 = C + (size_t)row0 * 256 + col;
            if (row0 < M)
                *(float2*)c0 = make_float2(acc[mt][nt][0], acc[mt][nt][1]);
            if (row0 + 8 < M)
                *(float2*)(c0 + 8 * 256) = make_float2(acc[mt][nt][2], acc[mt][nt][3]);
        }
    }
}

// ---------------- CSR gather + self loop + bias + relu: one warp per dst node ----
__global__ __launch_bounds__(256) void k_gather(const float* __restrict__ H,
                                                float* __restrict__ OUT,
                                                const float* __restrict__ bias) {
    int node = blockIdx.x * 8 + (threadIdx.x >> 5);
    int lane = threadIdx.x & 31;
    if (node >= N_NODES) return;
    int e0 = g_rowstart[node];
    int e1 = g_rowstart[node + 1];
    const float4* __restrict__ H4 = (const float4*)H;

    float4 a0 = make_float4(0.f, 0.f, 0.f, 0.f);
    float4 a1 = make_float4(0.f, 0.f, 0.f, 0.f);

    int e = e0;
    for (; e + 2 <= e1; e += 2) {
        int   s0 = g_esrc[e],     s1 = g_esrc[e + 1];
        float n0 = g_enorm[e],    n1 = g_enorm[e + 1];
        float4 v00 = H4[(size_t)s0 * 64 + lane];
        float4 v01 = H4[(size_t)s0 * 64 + 32 + lane];
        float4 v10 = H4[(size_t)s1 * 64 + lane];
        float4 v11 = H4[(size_t)s1 * 64 + 32 + lane];
        a0.x = fmaf(n0, v00.x, a0.x); a0.y = fmaf(n0, v00.y, a0.y);
        a0.z = fmaf(n0, v00.z, a0.z); a0.w = fmaf(n0, v00.w, a0.w);
        a1.x = fmaf(n0, v01.x, a1.x); a1.y = fmaf(n0, v01.y, a1.y);
        a1.z = fmaf(n0, v01.z, a1.z); a1.w = fmaf(n0, v01.w, a1.w);
        a0.x = fmaf(n1, v10.x, a0.x); a0.y = fmaf(n1, v10.y, a0.y);
        a0.z = fmaf(n1, v10.z, a0.z); a0.w = fmaf(n1, v10.w, a0.w);
        a1.x = fmaf(n1, v11.x, a1.x); a1.y = fmaf(n1, v11.y, a1.y);
        a1.z = fmaf(n1, v11.z, a1.z); a1.w = fmaf(n1, v11.w, a1.w);
    }
    if (e < e1) {
        int   s0 = g_esrc[e];
        float n0 = g_enorm[e];
        float4 v00 = H4[(size_t)s0 * 64 + lane];
        float4 v01 = H4[(size_t)s0 * 64 + 32 + lane];
        a0.x = fmaf(n0, v00.x, a0.x); a0.y = fmaf(n0, v00.y, a0.y);
        a0.z = fmaf(n0, v00.z, a0.z); a0.w = fmaf(n0, v00.w, a0.w);
        a1.x = fmaf(n0, v01.x, a1.x); a1.y = fmaf(n0, v01.y, a1.y);
        a1.z = fmaf(n0, v01.z, a1.z); a1.w = fmaf(n0, v01.w, a1.w);
    }

    // self loop + bias + relu
    float di = g_dinv[node];
    float sl = di * di;
    float4 h0 = H4[(size_t)node * 64 + lane];
    float4 h1 = H4[(size_t)node * 64 + 32 + lane];
    float4 b0 = ((const float4*)bias)[lane];
    float4 b1 = ((const float4*)bias)[32 + lane];
    a0.x = fmaxf(fmaf(sl, h0.x, a0.x) + b0.x, 0.f);
    a0.y = fmaxf(fmaf(sl, h0.y, a0.y) + b0.y, 0.f);
    a0.z = fmaxf(fmaf(sl, h0.z, a0.z) + b0.z, 0.f);
    a0.w = fmaxf(fmaf(sl, h0.w, a0.w) + b0.w, 0.f);
    a1.x = fmaxf(fmaf(sl, h1.x, a1.x) + b1.x, 0.f);
    a1.y = fmaxf(fmaf(sl, h1.y, a1.y) + b1.y, 0.f);
    a1.z = fmaxf(fmaf(sl, h1.z, a1.z) + b1.z, 0.f);
    a1.w = fmaxf(fmaf(sl, h1.w, a1.w) + b1.w, 0.f);

    float4* O4 = (float4*)OUT;
    O4[(size_t)node * 64 + lane]      = a0;
    O4[(size_t)node * 64 + 32 + lane] = a1;
}

// ---------------- pooling over h2 (batch sorted -> per-block pre-reduce) ----------
#define NPB 128
__global__ __launch_bounds__(256) void k_pool(const float* __restrict__ H2,
                                              const int* __restrict__ batch) {
    int f  = threadIdx.x;
    int n0 = blockIdx.x * NPB;
    int n1 = min(n0 + NPB, N_NODES);
    int cur_g = batch[n0];
    float s = 0.f, m = 0.f;
    for (int n = n0; n < n1; ++n) {
        int g = batch[n];
        if (g != cur_g) {
            atomicAdd(&g_psum[cur_g * F + f], s);
            atomicMax(&g_pmax[cur_g * F + f], __float_as_uint(m));
            s = 0.f; m = 0.f; cur_g = g;
        }
        float v = H2[(size_t)n * F + f];
        s += v;
        m = fmaxf(m, v);
    }
    atomicAdd(&g_psum[cur_g * F + f], s);
    atomicMax(&g_pmax[cur_g * F + f], __float_as_uint(m));
}

// ---------------- final FC: out[64,128] = [mean|max|sum] @ Wfc + bfc ----------------
__global__ __launch_bounds__(128) void k_fc(const float* __restrict__ Wfc,
                                            const float* __restrict__ bfc,
                                            float* __restrict__ out) {
    int g = blockIdx.x;
    int j = threadIdx.x;
    float cinv = 1.f / fmaxf(g_cnt[g], 1.f);
    float acc = bfc[j];
#pragma unroll 4
    for (int k = 0; k < F; k++)
        acc = fmaf(g_psum[g * F + k] * cinv, Wfc[(size_t)k * F_OUT_ + j], acc);
#pragma unroll 4
    for (int k = 0; k < F; k++)
        acc = fmaf(__uint_as_float(g_pmax[g * F + k]), Wfc[(size_t)(F + k) * F_OUT_ + j], acc);
#pragma unroll 4
    for (int k = 0; k < F; k++)
        acc = fmaf(g_psum[g * F + k], Wfc[(size_t)(2 * F + k) * F_OUT_ + j], acc);
    out[(size_t)g * F_OUT_ + j] = acc;
}

// ---------------- launcher ----------------
extern "C" void kernel_launch(void* const* d_in, const int* in_sizes, int n_in,
                              void* d_out, int out_size) {
    const float* x     = (const float*)d_in[0];
    const int*   ei    = (const int*)d_in[1];
    const int*   batch = (const int*)d_in[2];
    int w = n_in - 6;
    const float* W1  = (const float*)d_in[w + 0];
    const float* b1  = (const float*)d_in[w + 1];
    const float* W2  = (const float*)d_in[w + 2];
    const float* b2  = (const float*)d_in[w + 3];
    const float* Wfc = (const float*)d_in[w + 4];
    const float* bfc = (const float*)d_in[w + 5];
    float* out = (float*)d_out;

    const int* src = ei;
    const int* dst = ei + N_EDGES;

    float* buf0; cudaGetSymbolAddress((void**)&buf0, g_buf0);
    float* buf1; cudaGetSymbolAddress((void**)&buf1, g_buf1);
    __nv_bfloat16 *B1h, *B1l, *B2h, *B2l;
    cudaGetSymbolAddress((void**)&B1h, g_B1h);
    cudaGetSymbolAddress((void**)&B1l, g_B1l);
    cudaGetSymbolAddress((void**)&B2h, g_B2h);
    cudaGetSymbolAddress((void**)&B2l, g_B2l);

    dim3 ggrid(2, (N_NODES + BM - 1) / BM);   // (2, 391)
    const int gather_blocks = (N_NODES + 7) / 8;

    k_init_small<<<256, 256>>>();
    k_convB<<<(F * F + 255) / 256, 256>>>(W1, B1h, B1l);
    k_convB<<<(F * F + 255) / 256, 256>>>(W2, B2h, B2l);
    k_deg<<<(N_EDGES + 255) / 256, 256>>>(dst);
    k_dinv<<<(N_NODES + 255) / 256, 256>>>(batch);
    k_scan<<<1, 1024>>>();
    k_fill<<<(N_EDGES + 255) / 256, 256>>>(src, dst);

    // layer 1
    k_gemm_tc<<<ggrid, 256>>>(x, B1h, B1l, buf0, N_NODES);
    k_gather<<<gather_blocks, 256>>>(buf0, buf1, b1);       // buf1 := h1

    // layer 2
    k_gemm_tc<<<ggrid, 256>>>(buf1, B2h, B2l, buf0, N_NODES);
    k_gather<<<gather_blocks, 256>>>(buf0, buf1, b2);       // buf1 := h2
    k_pool<<<(N_NODES + NPB - 1) / NPB, 256>>>(buf1, batch);

    // readout
    k_fc<<<N_GRAPHS, 128>>>(Wfc, bfc, out);
    (void)in_sizes; (void)out_size;
}

// round 10
// speedup vs baseline: 2.9873x; 1.1175x over previous
#include <cuda_runtime.h>
#include <cuda_bf16.h>
#include <cuda_fp16.h>
#include <math.h>
#include <stdint.h>

// Problem constants (fixed by the dataset)
#define N_NODES   50000
#define N_EDGES   800000
#define N_GRAPHS  64
#define F         256      // F_IN == F_HID
#define F_OUT_    128
#define NF        (N_NODES * F)   // 12,800,000

// ---------------- scratch (device globals; no allocs allowed) ----------------
__device__ __half   g_h0[NF];            // h_lin (x@W1, later h1@W2)  [fp16]
__device__ __half   g_h1[NF];            // h1 / h2                    [fp16]
__device__ float    g_dinv[N_NODES];     // rsqrt(1+deg)
__device__ int      g_degi[N_NODES];     // in-degree (excl self loop)
__device__ int      g_rowstart[N_NODES + 1];
__device__ int      g_cursor[N_NODES];
__device__ int      g_esrc[N_EDGES];     // CSR by dst: src ids
__device__ float    g_enorm[N_EDGES];    // CSR by dst: dinv[src]*dinv[dst]
__device__ float    g_cnt[N_GRAPHS];     // nodes per graph
__device__ float    g_psum[N_GRAPHS * F];
__device__ unsigned g_pmax[N_GRAPHS * F]; // float bits; valid since vals >= 0

// bf16-split weights (hi/lo) for both layers
__device__ __nv_bfloat16 g_B1h[F * F], g_B1l[F * F];
__device__ __nv_bfloat16 g_B2h[F * F], g_B2l[F * F];

// ---------------- init ----------------
__global__ void k_init_small() {
    int i = blockIdx.x * blockDim.x + threadIdx.x;
    int stride = gridDim.x * blockDim.x;
    for (int j = i; j < N_NODES; j += stride) g_degi[j] = 0;
    for (int j = i; j < N_GRAPHS * F; j += stride) { g_psum[j] = 0.0f; g_pmax[j] = 0u; }
    for (int j = i; j < N_GRAPHS; j += stride) g_cnt[j] = 0.0f;
}

// ---------------- degree / norm ----------------
__global__ void k_deg(const int* __restrict__ dst) {
    int e = blockIdx.x * blockDim.x + threadIdx.x;
    if (e < N_EDGES) atomicAdd(&g_degi[dst[e]], 1);
}

__global__ void k_dinv(const int* __restrict__ batch) {
    int i = blockIdx.x * blockDim.x + threadIdx.x;
    if (i < N_NODES) {
        g_dinv[i] = rsqrtf(1.0f + (float)g_degi[i]);   // self loop included
        atomicAdd(&g_cnt[batch[i]], 1.0f);
    }
}

// ---------------- exclusive scan of degrees -> rowstart/cursor (1 block) ----------------
__global__ __launch_bounds__(1024) void k_scan() {
    __shared__ int part[1024];
    int t = threadIdx.x;
    const int CH = (N_NODES + 1023) / 1024;     // 49
    int s0 = t * CH;
    int s1 = min(s0 + CH, N_NODES);
    int sum = 0;
    for (int i = s0; i < s1; i++) sum += g_degi[i];
    part[t] = sum;
    __syncthreads();
    for (int off = 1; off < 1024; off <<= 1) {
        int v = (t >= off) ? part[t - off] : 0;
        __syncthreads();
        part[t] += v;
        __syncthreads();
    }
    int excl = (t == 0) ? 0 : part[t - 1];
    for (int i = s0; i < s1; i++) {
        g_rowstart[i] = excl;
        g_cursor[i] = excl;
        excl += g_degi[i];
    }
    if (t == 1023) g_rowstart[N_NODES] = part[1023];   // grand total (inclusive scan top)
}

// ---------------- CSR fill: place (src, norm) per edge, grouped by dst ----------------
__global__ void k_fill(const int* __restrict__ src, const int* __restrict__ dst) {
    int e = blockIdx.x * blockDim.x + threadIdx.x;
    if (e < N_EDGES) {
        int s = src[e], d = dst[e];
        int pos = atomicAdd(&g_cursor[d], 1);
        g_esrc[pos] = s;
        g_enorm[pos] = g_dinv[s] * g_dinv[d];
    }
}

// ---------------- weight split: W1,W2 -> bf16 hi/lo (one launch) ----------------
__global__ void k_convB(const float* __restrict__ W1, const float* __restrict__ W2) {
    int i = blockIdx.x * blockDim.x + threadIdx.x;
    if (i < F * F) {
        float v = W1[i];
        __nv_bfloat16 h = __float2bfloat16(v);
        g_B1h[i] = h;
        g_B1l[i] = __float2bfloat16(v - __bfloat162float(h));
        float v2 = W2[i];
        __nv_bfloat16 h2 = __float2bfloat16(v2);
        g_B2h[i] = h2;
        g_B2l[i] = __float2bfloat16(v2 - __bfloat162float(h2));
    }
}

// ---------------- tensor-core GEMM: C[M,256] = A[M,256] @ W[256,256] ----------
// bf16 split: C ≈ Ahi*Bhi + Ahi*Blo + Alo*Bhi (fp32 accumulate), C stored fp16
#define BM 128
#define BN 128
#define KC 32
#define APAD 40
#define BPAD 136

__device__ __forceinline__ void ldsm_x4(uint32_t& r0, uint32_t& r1, uint32_t& r2, uint32_t& r3,
                                        uint32_t addr) {
    asm volatile("ldmatrix.sync.aligned.m8n8.x4.shared.b16 {%0,%1,%2,%3}, [%4];\n"
                 : "=r"(r0), "=r"(r1), "=r"(r2), "=r"(r3) : "r"(addr));
}
__device__ __forceinline__ void ldsm_x4t(uint32_t& r0, uint32_t& r1, uint32_t& r2, uint32_t& r3,
                                         uint32_t addr) {
    asm volatile("ldmatrix.sync.aligned.m8n8.x4.trans.shared.b16 {%0,%1,%2,%3}, [%4];\n"
                 : "=r"(r0), "=r"(r1), "=r"(r2), "=r"(r3) : "r"(addr));
}
__device__ __forceinline__ void mma_bf16(float* c, const uint32_t* a, uint32_t b0, uint32_t b1) {
    asm volatile("mma.sync.aligned.m16n8k16.row.col.f32.bf16.bf16.f32 "
                 "{%0,%1,%2,%3}, {%4,%5,%6,%7}, {%8,%9}, {%0,%1,%2,%3};\n"
                 : "+f"(c[0]), "+f"(c[1]), "+f"(c[2]), "+f"(c[3])
                 : "r"(a[0]), "r"(a[1]), "r"(a[2]), "r"(a[3]), "r"(b0), "r"(b1));
}
__device__ __forceinline__ uint32_t pack_bf2(__nv_bfloat16 a, __nv_bfloat16 b) {
    __nv_bfloat162 p = __halves2bfloat162(a, b);
    return *(uint32_t*)&p;
}

template <bool HALF_A>
__global__ __launch_bounds__(256) void k_gemm_tc(const void* __restrict__ Aptr,
                                                 const __nv_bfloat16* __restrict__ Bh,
                                                 const __nv_bfloat16* __restrict__ Bl,
                                                 __half* __restrict__ C, int M) {
    __shared__ __nv_bfloat16 sAh[BM * APAD];
    __shared__ __nv_bfloat16 sAl[BM * APAD];
    __shared__ __nv_bfloat16 sBh[KC * BPAD];
    __shared__ __nv_bfloat16 sBl[KC * BPAD];

    const int tid  = threadIdx.x;
    const int lane = tid & 31;
    const int wid  = tid >> 5;
    const int wm   = wid >> 1;
    const int wn   = wid & 1;
    const int bm   = blockIdx.y * BM;
    const int bn   = blockIdx.x * BN;

    const int lr = lane & 7;
    const int lg = lane >> 3;
    const int rowoff = ((lg & 1) << 3) + lr;
    const int coloff = (lg & 2) << 2;

    float acc[2][8][4];
#pragma unroll
    for (int i = 0; i < 2; i++)
#pragma unroll
        for (int j = 0; j < 8; j++)
#pragma unroll
            for (int k = 0; k < 4; k++) acc[i][j][k] = 0.f;

    for (int kk = 0; kk < 256; kk += KC) {
        // ---- load A tile [BM x KC], split to bf16 hi/lo in SMEM ----
#pragma unroll
        for (int i = 0; i < 4; i++) {
            int idx = i * 256 + tid;            // 0..1023 quad slots
            int r = idx >> 3;                   // 0..127
            int c = (idx & 7) * 4;              // 0..28
            int grow = bm + r;
            float vx = 0.f, vy = 0.f, vz = 0.f, vw = 0.f;
            if (grow < M) {
                if (HALF_A) {
                    const __half* A = (const __half*)Aptr;
                    uint2 q = *(const uint2*)(A + (size_t)grow * 256 + kk + c);
                    __half2 p0 = *(__half2*)&q.x;
                    __half2 p1 = *(__half2*)&q.y;
                    float2 f0 = __half22float2(p0);
                    float2 f1 = __half22float2(p1);
                    vx = f0.x; vy = f0.y; vz = f1.x; vw = f1.y;
                } else {
                    const float* A = (const float*)Aptr;
                    float4 v = *(const float4*)(A + (size_t)grow * 256 + kk + c);
                    vx = v.x; vy = v.y; vz = v.z; vw = v.w;
                }
            }
            __nv_bfloat16 h0 = __float2bfloat16(vx), h1 = __float2bfloat16(vy);
            __nv_bfloat16 h2 = __float2bfloat16(vz), h3 = __float2bfloat16(vw);
            __nv_bfloat16 l0 = __float2bfloat16(vx - __bfloat162float(h0));
            __nv_bfloat16 l1 = __float2bfloat16(vy - __bfloat162float(h1));
            __nv_bfloat16 l2 = __float2bfloat16(vz - __bfloat162float(h2));
            __nv_bfloat16 l3 = __float2bfloat16(vw - __bfloat162float(h3));
            uint32_t* ph = (uint32_t*)&sAh[r * APAD + c];
            uint32_t* pl = (uint32_t*)&sAl[r * APAD + c];
            ph[0] = pack_bf2(h0, h1); ph[1] = pack_bf2(h2, h3);
            pl[0] = pack_bf2(l0, l1); pl[1] = pack_bf2(l2, l3);
        }
        // ---- load B tile [KC x BN] bf16 hi & lo ----
#pragma unroll
        for (int i = 0; i < 2; i++) {
            int idx = i * 256 + tid;
            int r = idx >> 4;
            int c = (idx & 15) * 8;
            uint4 vh = *(const uint4*)(Bh + (size_t)(kk + r) * 256 + bn + c);
            uint4 vl = *(const uint4*)(Bl + (size_t)(kk + r) * 256 + bn + c);
            *(uint4*)&sBh[r * BPAD + c] = vh;
            *(uint4*)&sBl[r * BPAD + c] = vl;
        }
        __syncthreads();

#pragma unroll
        for (int kf = 0; kf < KC; kf += 16) {
            uint32_t ah[2][4], al[2][4];
#pragma unroll
            for (int mt = 0; mt < 2; mt++) {
                int rowi = (wm * 32 + mt * 16 + rowoff) * APAD + kf + coloff;
                ldsm_x4(ah[mt][0], ah[mt][1], ah[mt][2], ah[mt][3],
                        (uint32_t)__cvta_generic_to_shared(&sAh[rowi]));
                ldsm_x4(al[mt][0], al[mt][1], al[mt][2], al[mt][3],
                        (uint32_t)__cvta_generic_to_shared(&sAl[rowi]));
            }
            uint32_t bh[4][4], bl[4][4];
#pragma unroll
            for (int nt4 = 0; nt4 < 4; nt4++) {
                int ci = (kf + rowoff) * BPAD + wn * 64 + nt4 * 16 + coloff;
                ldsm_x4t(bh[nt4][0], bh[nt4][1], bh[nt4][2], bh[nt4][3],
                         (uint32_t)__cvta_generic_to_shared(&sBh[ci]));
                ldsm_x4t(bl[nt4][0], bl[nt4][1], bl[nt4][2], bl[nt4][3],
                         (uint32_t)__cvta_generic_to_shared(&sBl[ci]));
            }
#pragma unroll
            for (int mt = 0; mt < 2; mt++) {
#pragma unroll
                for (int nt4 = 0; nt4 < 4; nt4++) {
                    mma_bf16(acc[mt][nt4 * 2 + 0], ah[mt], bh[nt4][0], bh[nt4][1]);
                    mma_bf16(acc[mt][nt4 * 2 + 1], ah[mt], bh[nt4][2], bh[nt4][3]);
                    mma_bf16(acc[mt][nt4 * 2 + 0], ah[mt], bl[nt4][0], bl[nt4][1]);
                    mma_bf16(acc[mt][nt4 * 2 + 1], ah[mt], bl[nt4][2], bl[nt4][3]);
                    mma_bf16(acc[mt][nt4 * 2 + 0], al[mt], bh[nt4][0], bh[nt4][1]);
                    mma_bf16(acc[mt][nt4 * 2 + 1], al[mt], bh[nt4][2], bh[nt4][3]);
                }
            }
        }
        __syncthreads();
    }

    // ---- store C as fp16 ----
    const int gid2 = lane >> 2;
    const int tig  = lane & 3;
#pragma unroll
    for (int mt = 0; mt < 2; mt++) {
#pragma unroll
        for (int nt = 0; nt < 8; nt++) {
            int row0 = bm + wm * 32 + mt * 16 + gid2;
            int col  = bn + wn * 64 + nt * 8 + tig * 2;
            __half* c0 = C + (size_t)row0 * 256 + col;
            if (row0 < M)
                *(__half2*)c0 = __floats2half2_rn(acc[mt][nt][0], acc[mt][nt][1]);
            if (row0 + 8 < M)
                *(__half2*)(c0 + 8 * 256) = __floats2half2_rn(acc[mt][nt][2], acc[mt][nt][3]);
        }
    }
}

// ---------------- CSR gather + self loop + bias + relu: one warp per dst node ----
// fp16 rows: one uint4 (8 halfs) per lane covers the 256-feature row.
__global__ __launch_bounds__(256) void k_gather(const __half* __restrict__ H,
                                                __half* __restrict__ OUT,
                                                const float* __restrict__ bias) {
    int node = blockIdx.x * 8 + (threadIdx.x >> 5);
    int lane = threadIdx.x & 31;
    if (node >= N_NODES) return;
    int e0 = g_rowstart[node];
    int e1 = g_rowstart[node + 1];
    const uint4* __restrict__ H16 = (const uint4*)H;   // 8 halfs per uint4, 32 per row

    float a[8];
#pragma unroll
    for (int i = 0; i < 8; i++) a[i] = 0.f;

#define ACC8(q, n)                                                        \
    do {                                                                  \
        __half2 p0 = *(__half2*)&(q).x, p1 = *(__half2*)&(q).y;           \
        __half2 p2 = *(__half2*)&(q).z, p3 = *(__half2*)&(q).w;           \
        float2 f0 = __half22float2(p0), f1 = __half22float2(p1);          \
        float2 f2 = __half22float2(p2), f3 = __half22float2(p3);          \
        a[0] = fmaf(n, f0.x, a[0]); a[1] = fmaf(n, f0.y, a[1]);           \
        a[2] = fmaf(n, f1.x, a[2]); a[3] = fmaf(n, f1.y, a[3]);           \
        a[4] = fmaf(n, f2.x, a[4]); a[5] = fmaf(n, f2.y, a[5]);           \
        a[6] = fmaf(n, f3.x, a[6]); a[7] = fmaf(n, f3.y, a[7]);           \
    } while (0)

    int e = e0;
    for (; e + 4 <= e1; e += 4) {
        int   s0 = g_esrc[e],  s1 = g_esrc[e + 1], s2 = g_esrc[e + 2], s3 = g_esrc[e + 3];
        float n0 = g_enorm[e], n1 = g_enorm[e + 1], n2 = g_enorm[e + 2], n3 = g_enorm[e + 3];
        uint4 q0 = H16[(size_t)s0 * 32 + lane];
        uint4 q1 = H16[(size_t)s1 * 32 + lane];
        uint4 q2 = H16[(size_t)s2 * 32 + lane];
        uint4 q3 = H16[(size_t)s3 * 32 + lane];
        ACC8(q0, n0); ACC8(q1, n1); ACC8(q2, n2); ACC8(q3, n3);
    }
    for (; e < e1; e++) {
        int   s0 = g_esrc[e];
        float n0 = g_enorm[e];
        uint4 q0 = H16[(size_t)s0 * 32 + lane];
        ACC8(q0, n0);
    }

    // self loop + bias + relu
    float di = g_dinv[node];
    float sl = di * di;
    uint4 qs = H16[(size_t)node * 32 + lane];
    ACC8(qs, sl);

    float4 b0 = ((const float4*)bias)[lane * 2];
    float4 b1 = ((const float4*)bias)[lane * 2 + 1];
    a[0] = fmaxf(a[0] + b0.x, 0.f); a[1] = fmaxf(a[1] + b0.y, 0.f);
    a[2] = fmaxf(a[2] + b0.z, 0.f); a[3] = fmaxf(a[3] + b0.w, 0.f);
    a[4] = fmaxf(a[4] + b1.x, 0.f); a[5] = fmaxf(a[5] + b1.y, 0.f);
    a[6] = fmaxf(a[6] + b1.z, 0.f); a[7] = fmaxf(a[7] + b1.w, 0.f);

    uint4 o;
    __half2 o0 = __floats2half2_rn(a[0], a[1]);
    __half2 o1 = __floats2half2_rn(a[2], a[3]);
    __half2 o2 = __floats2half2_rn(a[4], a[5]);
    __half2 o3 = __floats2half2_rn(a[6], a[7]);
    o.x = *(uint32_t*)&o0; o.y = *(uint32_t*)&o1;
    o.z = *(uint32_t*)&o2; o.w = *(uint32_t*)&o3;
    ((uint4*)OUT)[(size_t)node * 32 + lane] = o;
#undef ACC8
}

// ---------------- pooling over h2 (batch sorted -> per-block pre-reduce) ----------
#define NPB 128
__global__ __launch_bounds__(256) void k_pool(const __half* __restrict__ H2,
                                              const int* __restrict__ batch) {
    int f  = threadIdx.x;
    int n0 = blockIdx.x * NPB;
    int n1 = min(n0 + NPB, N_NODES);
    int cur_g = batch[n0];
    float s = 0.f, m = 0.f;
    for (int n = n0; n < n1; ++n) {
        int g = batch[n];
        if (g != cur_g) {
            atomicAdd(&g_psum[cur_g * F + f], s);
            atomicMax(&g_pmax[cur_g * F + f], __float_as_uint(m));
            s = 0.f; m = 0.f; cur_g = g;
        }
        float v = __half2float(H2[(size_t)n * F + f]);
        s += v;
        m = fmaxf(m, v);
    }
    atomicAdd(&g_psum[cur_g * F + f], s);
    atomicMax(&g_pmax[cur_g * F + f], __float_as_uint(m));
}

// ---------------- final FC: out[64,128] = [mean|max|sum] @ Wfc + bfc ----------------
__global__ __launch_bounds__(128) void k_fc(const float* __restrict__ Wfc,
                                            const float* __restrict__ bfc,
                                            float* __restrict__ out) {
    int g = blockIdx.x;
    int j = threadIdx.x;
    float cinv = 1.f / fmaxf(g_cnt[g], 1.f);
    float acc = bfc[j];
#pragma unroll 4
    for (int k = 0; k < F; k++)
        acc = fmaf(g_psum[g * F + k] * cinv, Wfc[(size_t)k * F_OUT_ + j], acc);
#pragma unroll 4
    for (int k = 0; k < F; k++)
        acc = fmaf(__uint_as_float(g_pmax[g * F + k]), Wfc[(size_t)(F + k) * F_OUT_ + j], acc);
#pragma unroll 4
    for (int k = 0; k < F; k++)
        acc = fmaf(g_psum[g * F + k], Wfc[(size_t)(2 * F + k) * F_OUT_ + j], acc);
    out[(size_t)g * F_OUT_ + j] = acc;
}

// ---------------- launcher ----------------
extern "C" void kernel_launch(void* const* d_in, const int* in_sizes, int n_in,
                              void* d_out, int out_size) {
    const float* x     = (const float*)d_in[0];
    const int*   ei    = (const int*)d_in[1];
    const int*   batch = (const int*)d_in[2];
    int w = n_in - 6;
    const float* W1  = (const float*)d_in[w + 0];
    const float* b1  = (const float*)d_in[w + 1];
    const float* W2  = (const float*)d_in[w + 2];
    const float* b2  = (const float*)d_in[w + 3];
    const float* Wfc = (const float*)d_in[w + 4];
    const float* bfc = (const float*)d_in[w + 5];
    float* out = (float*)d_out;

    const int* src = ei;
    const int* dst = ei + N_EDGES;

    __half* h0; cudaGetSymbolAddress((void**)&h0, g_h0);
    __half* h1; cudaGetSymbolAddress((void**)&h1, g_h1);
    __nv_bfloat16 *B1h, *B1l, *B2h, *B2l;
    cudaGetSymbolAddress((void**)&B1h, g_B1h);
    cudaGetSymbolAddress((void**)&B1l, g_B1l);
    cudaGetSymbolAddress((void**)&B2h, g_B2h);
    cudaGetSymbolAddress((void**)&B2l, g_B2l);

    dim3 ggrid(2, (N_NODES + BM - 1) / BM);   // (2, 391)
    const int gather_blocks = (N_NODES + 7) / 8;

    k_init_small<<<256, 256>>>();
    k_convB<<<(F * F + 255) / 256, 256>>>(W1, W2);
    k_deg<<<(N_EDGES + 255) / 256, 256>>>(dst);
    k_dinv<<<(N_NODES + 255) / 256, 256>>>(batch);
    k_scan<<<1, 1024>>>();
    k_fill<<<(N_EDGES + 255) / 256, 256>>>(src, dst);

    // layer 1
    k_gemm_tc<false><<<ggrid, 256>>>(x, B1h, B1l, h0, N_NODES);
    k_gather<<<gather_blocks, 256>>>(h0, h1, b1);           // h1 := relu(agg + b1)

    // layer 2
    k_gemm_tc<true><<<ggrid, 256>>>(h1, B2h, B2l, h0, N_NODES);
    k_gather<<<gather_blocks, 256>>>(h0, h1, b2);           // h1 := h2
    k_pool<<<(N_NODES + NPB - 1) / NPB, 256>>>(h1, batch);

    // readout
    k_fc<<<N_GRAPHS, 128>>>(Wfc, bfc, out);
    (void)in_sizes; (void)out_size;
}

// round 11
// speedup vs baseline: 3.7807x; 1.2656x over previous
#include <cuda_runtime.h>
#include <cuda_fp16.h>
#include <math.h>
#include <stdint.h>

// Problem constants (fixed by the dataset)
#define N_NODES   50000
#define N_EDGES   800000
#define N_GRAPHS  64
#define F         256      // F_IN == F_HID
#define F_OUT_    128
#define NF        (N_NODES * F)   // 12,800,000

// ---------------- scratch (device globals; no allocs allowed) ----------------
__device__ __half   g_h0[NF];            // h_lin (x@W1, later h1@W2)  [fp16]
__device__ __half   g_h1[NF];            // h1 / h2                    [fp16]
__device__ float    g_dinv[N_NODES];     // rsqrt(1+deg)
__device__ int      g_degi[N_NODES];     // in-degree (excl self loop)
__device__ int      g_rowstart[N_NODES + 1];
__device__ int      g_cursor[N_NODES];
__device__ int      g_esrc[N_EDGES];     // CSR by dst: src ids
__device__ float    g_enorm[N_EDGES];    // CSR by dst: dinv[src]*dinv[dst]
__device__ float    g_cnt[N_GRAPHS];     // nodes per graph
__device__ float    g_psum[N_GRAPHS * F];
__device__ unsigned g_pmax[N_GRAPHS * F]; // float bits; valid since vals >= 0

// fp16-split weights (hi/lo) for both layers: W ≈ Wh + Wl (fp16 each, ~22 bits)
__device__ __half g_W1h[F * F], g_W1l[F * F];
__device__ __half g_W2h[F * F], g_W2l[F * F];

// ---------------- init ----------------
__global__ void k_init_small() {
    int i = blockIdx.x * blockDim.x + threadIdx.x;
    int stride = gridDim.x * blockDim.x;
    for (int j = i; j < N_NODES; j += stride) g_degi[j] = 0;
    for (int j = i; j < N_GRAPHS * F; j += stride) { g_psum[j] = 0.0f; g_pmax[j] = 0u; }
    for (int j = i; j < N_GRAPHS; j += stride) g_cnt[j] = 0.0f;
}

// ---------------- degree / norm ----------------
__global__ void k_deg(const int* __restrict__ dst) {
    int e = blockIdx.x * blockDim.x + threadIdx.x;
    if (e < N_EDGES) atomicAdd(&g_degi[dst[e]], 1);
}

__global__ void k_dinv() {
    int i = blockIdx.x * blockDim.x + threadIdx.x;
    if (i < N_NODES) g_dinv[i] = rsqrtf(1.0f + (float)g_degi[i]);  // self loop included
}

// ---------------- exclusive scan of degrees -> rowstart/cursor (1 block) ----------------
__global__ __launch_bounds__(1024) void k_scan() {
    __shared__ int part[1024];
    int t = threadIdx.x;
    const int CH = (N_NODES + 1023) / 1024;     // 49
    int s0 = t * CH;
    int s1 = min(s0 + CH, N_NODES);
    int sum = 0;
    for (int i = s0; i < s1; i++) sum += g_degi[i];
    part[t] = sum;
    __syncthreads();
    for (int off = 1; off < 1024; off <<= 1) {
        int v = (t >= off) ? part[t - off] : 0;
        __syncthreads();
        part[t] += v;
        __syncthreads();
    }
    int excl = (t == 0) ? 0 : part[t - 1];
    for (int i = s0; i < s1; i++) {
        g_rowstart[i] = excl;
        g_cursor[i] = excl;
        excl += g_degi[i];
    }
    if (t == 1023) g_rowstart[N_NODES] = part[1023];   // grand total
}

// ---------------- CSR fill: place (src, norm) per edge, grouped by dst ----------------
__global__ void k_fill(const int* __restrict__ src, const int* __restrict__ dst) {
    int e = blockIdx.x * blockDim.x + threadIdx.x;
    if (e < N_EDGES) {
        int s = src[e], d = dst[e];
        int pos = atomicAdd(&g_cursor[d], 1);
        g_esrc[pos] = s;
        g_enorm[pos] = g_dinv[s] * g_dinv[d];
    }
}

// ---------------- weight split: W1,W2 -> fp16 hi/lo (one launch) ----------------
__global__ void k_convW(const float* __restrict__ W1, const float* __restrict__ W2) {
    int i = blockIdx.x * blockDim.x + threadIdx.x;
    if (i < F * F) {
        float v = W1[i];
        __half h = __float2half_rn(v);
        g_W1h[i] = h;
        g_W1l[i] = __float2half_rn(v - __half2float(h));
        float v2 = W2[i];
        __half h2 = __float2half_rn(v2);
        g_W2h[i] = h2;
        g_W2l[i] = __float2half_rn(v2 - __half2float(h2));
    }
}

// ---------------- tensor-core GEMM: C[M,256] = A[M,256] @ (Wh+Wl)[256,256] ----
// A in fp16 (exact for layer 2; layer 1 converts fp32->fp16 at load).
// fp32 accumulate, C stored fp16. 2 MMA chains per tile (A*Wh + A*Wl).
#define BM 128
#define BN 128
#define KC 32
#define APAD 40
#define BPAD 136

__device__ __forceinline__ void ldsm_x4(uint32_t& r0, uint32_t& r1, uint32_t& r2, uint32_t& r3,
                                        uint32_t addr) {
    asm volatile("ldmatrix.sync.aligned.m8n8.x4.shared.b16 {%0,%1,%2,%3}, [%4];\n"
                 : "=r"(r0), "=r"(r1), "=r"(r2), "=r"(r3) : "r"(addr));
}
__device__ __forceinline__ void ldsm_x4t(uint32_t& r0, uint32_t& r1, uint32_t& r2, uint32_t& r3,
                                         uint32_t addr) {
    asm volatile("ldmatrix.sync.aligned.m8n8.x4.trans.shared.b16 {%0,%1,%2,%3}, [%4];\n"
                 : "=r"(r0), "=r"(r1), "=r"(r2), "=r"(r3) : "r"(addr));
}
__device__ __forceinline__ void mma_fp16(float* c, const uint32_t* a, uint32_t b0, uint32_t b1) {
    asm volatile("mma.sync.aligned.m16n8k16.row.col.f32.f16.f16.f32 "
                 "{%0,%1,%2,%3}, {%4,%5,%6,%7}, {%8,%9}, {%0,%1,%2,%3};\n"
                 : "+f"(c[0]), "+f"(c[1]), "+f"(c[2]), "+f"(c[3])
                 : "r"(a[0]), "r"(a[1]), "r"(a[2]), "r"(a[3]), "r"(b0), "r"(b1));
}

template <bool HALF_A>
__global__ __launch_bounds__(256) void k_gemm_tc(const void* __restrict__ Aptr,
                                                 const __half* __restrict__ Bh,
                                                 const __half* __restrict__ Bl,
                                                 __half* __restrict__ C, int M) {
    __shared__ __half sA[BM * APAD];
    __shared__ __half sBh[KC * BPAD];
    __shared__ __half sBl[KC * BPAD];

    const int tid  = threadIdx.x;
    const int lane = tid & 31;
    const int wid  = tid >> 5;
    const int wm   = wid >> 1;
    const int wn   = wid & 1;
    const int bm   = blockIdx.y * BM;
    const int bn   = blockIdx.x * BN;

    const int lr = lane & 7;
    const int lg = lane >> 3;
    const int rowoff = ((lg & 1) << 3) + lr;
    const int coloff = (lg & 2) << 2;

    float acc[2][8][4];
#pragma unroll
    for (int i = 0; i < 2; i++)
#pragma unroll
        for (int j = 0; j < 8; j++)
#pragma unroll
            for (int k = 0; k < 4; k++) acc[i][j][k] = 0.f;

    for (int kk = 0; kk < 256; kk += KC) {
        // ---- load A tile [BM x KC] fp16 into SMEM ----
#pragma unroll
        for (int i = 0; i < 4; i++) {
            int idx = i * 256 + tid;            // 0..1023 quad(4-half) slots
            int r = idx >> 3;                   // 0..127
            int c = (idx & 7) * 4;              // 0..28
            int grow = bm + r;
            uint32_t p0 = 0, p1 = 0;
            if (grow < M) {
                if (HALF_A) {
                    const __half* A = (const __half*)Aptr;
                    uint2 q = *(const uint2*)(A + (size_t)grow * 256 + kk + c);
                    p0 = q.x; p1 = q.y;
                } else {
                    const float* A = (const float*)Aptr;
                    float4 v = *(const float4*)(A + (size_t)grow * 256 + kk + c);
                    __half2 h0 = __floats2half2_rn(v.x, v.y);
                    __half2 h1 = __floats2half2_rn(v.z, v.w);
                    p0 = *(uint32_t*)&h0; p1 = *(uint32_t*)&h1;
                }
            }
            uint32_t* pa = (uint32_t*)&sA[r * APAD + c];
            pa[0] = p0; pa[1] = p1;
        }
        // ---- load B tile [KC x BN] fp16 hi & lo ----
#pragma unroll
        for (int i = 0; i < 2; i++) {
            int idx = i * 256 + tid;
            int r = idx >> 4;
            int c = (idx & 15) * 8;
            uint4 vh = *(const uint4*)(Bh + (size_t)(kk + r) * 256 + bn + c);
            uint4 vl = *(const uint4*)(Bl + (size_t)(kk + r) * 256 + bn + c);
            *(uint4*)&sBh[r * BPAD + c] = vh;
            *(uint4*)&sBl[r * BPAD + c] = vl;
        }
        __syncthreads();

#pragma unroll
        for (int kf = 0; kf < KC; kf += 16) {
            uint32_t ah[2][4];
#pragma unroll
            for (int mt = 0; mt < 2; mt++) {
                int rowi = (wm * 32 + mt * 16 + rowoff) * APAD + kf + coloff;
                ldsm_x4(ah[mt][0], ah[mt][1], ah[mt][2], ah[mt][3],
                        (uint32_t)__cvta_generic_to_shared(&sA[rowi]));
            }
            uint32_t bh[4][4], bl[4][4];
#pragma unroll
            for (int nt4 = 0; nt4 < 4; nt4++) {
                int ci = (kf + rowoff) * BPAD + wn * 64 + nt4 * 16 + coloff;
                ldsm_x4t(bh[nt4][0], bh[nt4][1], bh[nt4][2], bh[nt4][3],
                         (uint32_t)__cvta_generic_to_shared(&sBh[ci]));
                ldsm_x4t(bl[nt4][0], bl[nt4][1], bl[nt4][2], bl[nt4][3],
                         (uint32_t)__cvta_generic_to_shared(&sBl[ci]));
            }
#pragma unroll
            for (int mt = 0; mt < 2; mt++) {
#pragma unroll
                for (int nt4 = 0; nt4 < 4; nt4++) {
                    mma_fp16(acc[mt][nt4 * 2 + 0], ah[mt], bh[nt4][0], bh[nt4][1]);
                    mma_fp16(acc[mt][nt4 * 2 + 1], ah[mt], bh[nt4][2], bh[nt4][3]);
                    mma_fp16(acc[mt][nt4 * 2 + 0], ah[mt], bl[nt4][0], bl[nt4][1]);
                    mma_fp16(acc[mt][nt4 * 2 + 1], ah[mt], bl[nt4][2], bl[nt4][3]);
                }
            }
        }
        __syncthreads();
    }

    // ---- store C as fp16 ----
    const int gid2 = lane >> 2;
    const int tig  = lane & 3;
#pragma unroll
    for (int mt = 0; mt < 2; mt++) {
#pragma unroll
        for (int nt = 0; nt < 8; nt++) {
            int row0 = bm + wm * 32 + mt * 16 + gid2;
            int col  = bn + wn * 64 + nt * 8 + tig * 2;
            __half* c0 = C + (size_t)row0 * 256 + col;
            if (row0 < M)
                *(__half2*)c0 = __floats2half2_rn(acc[mt][nt][0], acc[mt][nt][1]);
            if (row0 + 8 < M)
                *(__half2*)(c0 + 8 * 256) = __floats2half2_rn(acc[mt][nt][2], acc[mt][nt][3]);
        }
    }
}

// ---------------- CSR gather + self loop + bias + relu: one warp per dst node ----
__global__ __launch_bounds__(256) void k_gather(const __half* __restrict__ H,
                                                __half* __restrict__ OUT,
                                                const float* __restrict__ bias) {
    int node = blockIdx.x * 8 + (threadIdx.x >> 5);
    int lane = threadIdx.x & 31;
    if (node >= N_NODES) return;
    int e0 = g_rowstart[node];
    int e1 = g_rowstart[node + 1];
    const uint4* __restrict__ H16 = (const uint4*)H;   // 8 halfs per uint4, 32 per row

    float a[8];
#pragma unroll
    for (int i = 0; i < 8; i++) a[i] = 0.f;

#define ACC8(q, n)                                                        \
    do {                                                                  \
        __half2 p0 = *(__half2*)&(q).x, p1 = *(__half2*)&(q).y;           \
        __half2 p2 = *(__half2*)&(q).z, p3 = *(__half2*)&(q).w;           \
        float2 f0 = __half22float2(p0), f1 = __half22float2(p1);          \
        float2 f2 = __half22float2(p2), f3 = __half22float2(p3);          \
        a[0] = fmaf(n, f0.x, a[0]); a[1] = fmaf(n, f0.y, a[1]);           \
        a[2] = fmaf(n, f1.x, a[2]); a[3] = fmaf(n, f1.y, a[3]);           \
        a[4] = fmaf(n, f2.x, a[4]); a[5] = fmaf(n, f2.y, a[5]);           \
        a[6] = fmaf(n, f3.x, a[6]); a[7] = fmaf(n, f3.y, a[7]);           \
    } while (0)

    int e = e0;
    for (; e + 4 <= e1; e += 4) {
        int   s0 = g_esrc[e],  s1 = g_esrc[e + 1], s2 = g_esrc[e + 2], s3 = g_esrc[e + 3];
        float n0 = g_enorm[e], n1 = g_enorm[e + 1], n2 = g_enorm[e + 2], n3 = g_enorm[e + 3];
        uint4 q0 = H16[(size_t)s0 * 32 + lane];
        uint4 q1 = H16[(size_t)s1 * 32 + lane];
        uint4 q2 = H16[(size_t)s2 * 32 + lane];
        uint4 q3 = H16[(size_t)s3 * 32 + lane];
        ACC8(q0, n0); ACC8(q1, n1); ACC8(q2, n2); ACC8(q3, n3);
    }
    for (; e < e1; e++) {
        int   s0 = g_esrc[e];
        float n0 = g_enorm[e];
        uint4 q0 = H16[(size_t)s0 * 32 + lane];
        ACC8(q0, n0);
    }

    // self loop + bias + relu
    float di = g_dinv[node];
    float sl = di * di;
    uint4 qs = H16[(size_t)node * 32 + lane];
    ACC8(qs, sl);

    float4 b0 = ((const float4*)bias)[lane * 2];
    float4 b1 = ((const float4*)bias)[lane * 2 + 1];
    a[0] = fmaxf(a[0] + b0.x, 0.f); a[1] = fmaxf(a[1] + b0.y, 0.f);
    a[2] = fmaxf(a[2] + b0.z, 0.f); a[3] = fmaxf(a[3] + b0.w, 0.f);
    a[4] = fmaxf(a[4] + b1.x, 0.f); a[5] = fmaxf(a[5] + b1.y, 0.f);
    a[6] = fmaxf(a[6] + b1.z, 0.f); a[7] = fmaxf(a[7] + b1.w, 0.f);

    uint4 o;
    __half2 o0 = __floats2half2_rn(a[0], a[1]);
    __half2 o1 = __floats2half2_rn(a[2], a[3]);
    __half2 o2 = __floats2half2_rn(a[4], a[5]);
    __half2 o3 = __floats2half2_rn(a[6], a[7]);
    o.x = *(uint32_t*)&o0; o.y = *(uint32_t*)&o1;
    o.z = *(uint32_t*)&o2; o.w = *(uint32_t*)&o3;
    ((uint4*)OUT)[(size_t)node * 32 + lane] = o;
#undef ACC8
}

// ---------------- pooling over h2 + per-graph node counts ----------------
#define NPB 128
__global__ __launch_bounds__(256) void k_pool(const __half* __restrict__ H2,
                                              const int* __restrict__ batch) {
    int f  = threadIdx.x;
    int n0 = blockIdx.x * NPB;
    int n1 = min(n0 + NPB, N_NODES);
    int cur_g = batch[n0];
    float s = 0.f, m = 0.f;
    int cnt = 0;
    for (int n = n0; n < n1; ++n) {
        int g = batch[n];                       // uniform across block
        if (g != cur_g) {
            atomicAdd(&g_psum[cur_g * F + f], s);
            atomicMax(&g_pmax[cur_g * F + f], __float_as_uint(m));
            if (f == 0) atomicAdd(&g_cnt[cur_g], (float)cnt);
            s = 0.f; m = 0.f; cnt = 0; cur_g = g;
        }
        float v = __half2float(H2[(size_t)n * F + f]);
        s += v;
        m = fmaxf(m, v);
        cnt++;
    }
    atomicAdd(&g_psum[cur_g * F + f], s);
    atomicMax(&g_pmax[cur_g * F + f], __float_as_uint(m));
    if (f == 0) atomicAdd(&g_cnt[cur_g], (float)cnt);
}

// ---------------- final FC: out[64,128] = [mean|max|sum] @ Wfc + bfc ----------------
__global__ __launch_bounds__(128) void k_fc(const float* __restrict__ Wfc,
                                            const float* __restrict__ bfc,
                                            float* __restrict__ out) {
    int g = blockIdx.x;
    int j = threadIdx.x;
    float cinv = 1.f / fmaxf(g_cnt[g], 1.f);
    float acc = bfc[j];
#pragma unroll 4
    for (int k = 0; k < F; k++)
        acc = fmaf(g_psum[g * F + k] * cinv, Wfc[(size_t)k * F_OUT_ + j], acc);
#pragma unroll 4
    for (int k = 0; k < F; k++)
        acc = fmaf(__uint_as_float(g_pmax[g * F + k]), Wfc[(size_t)(F + k) * F_OUT_ + j], acc);
#pragma unroll 4
    for (int k = 0; k < F; k++)
        acc = fmaf(g_psum[g * F + k], Wfc[(size_t)(2 * F + k) * F_OUT_ + j], acc);
    out[(size_t)g * F_OUT_ + j] = acc;
}

// ---------------- launcher ----------------
extern "C" void kernel_launch(void* const* d_in, const int* in_sizes, int n_in,
                              void* d_out, int out_size) {
    const float* x     = (const float*)d_in[0];
    const int*   ei    = (const int*)d_in[1];
    const int*   batch = (const int*)d_in[2];
    int w = n_in - 6;
    const float* W1  = (const float*)d_in[w + 0];
    const float* b1  = (const float*)d_in[w + 1];
    const float* W2  = (const float*)d_in[w + 2];
    const float* b2  = (const float*)d_in[w + 3];
    const float* Wfc = (const float*)d_in[w + 4];
    const float* bfc = (const float*)d_in[w + 5];
    float* out = (float*)d_out;

    const int* src = ei;
    const int* dst = ei + N_EDGES;

    __half* h0; cudaGetSymbolAddress((void**)&h0, g_h0);
    __half* h1; cudaGetSymbolAddress((void**)&h1, g_h1);
    __half *W1h, *W1l, *W2h, *W2l;
    cudaGetSymbolAddress((void**)&W1h, g_W1h);
    cudaGetSymbolAddress((void**)&W1l, g_W1l);
    cudaGetSymbolAddress((void**)&W2h, g_W2h);
    cudaGetSymbolAddress((void**)&W2l, g_W2l);

    dim3 ggrid(2, (N_NODES + BM - 1) / BM);   // (2, 391)
    const int gather_blocks = (N_NODES + 7) / 8;

    k_init_small<<<256, 256>>>();
    k_convW<<<(F * F + 255) / 256, 256>>>(W1, W2);
    k_deg<<<(N_EDGES + 255) / 256, 256>>>(dst);
    k_dinv<<<(N_NODES + 255) / 256, 256>>>();
    k_scan<<<1, 1024>>>();
    k_fill<<<(N_EDGES + 255) / 256, 256>>>(src, dst);

    // layer 1
    k_gemm_tc<false><<<ggrid, 256>>>(x, W1h, W1l, h0, N_NODES);
    k_gather<<<gather_blocks, 256>>>(h0, h1, b1);           // h1 := relu(agg + b1)

    // layer 2
    k_gemm_tc<true><<<ggrid, 256>>>(h1, W2h, W2l, h0, N_NODES);
    k_gather<<<gather_blocks, 256>>>(h0, h1, b2);           // h1 := h2
    k_pool<<<(N_NODES + NPB - 1) / NPB, 256>>>(h1, batch);

    // readout
    k_fc<<<N_GRAPHS, 128>>>(Wfc, bfc, out);
    (void)in_sizes; (void)out_size;
}

// round 13
// speedup vs baseline: 3.8324x; 1.0137x over previous
#include <cuda_runtime.h>
#include <cuda_fp16.h>
#include <math.h>
#include <stdint.h>

// Problem constants (fixed by the dataset)
#define N_NODES   50000
#define N_EDGES   800000
#define N_GRAPHS  64
#define F         256      // F_IN == F_HID
#define F_OUT_    128
#define NF        (N_NODES * F)   // 12,800,000

// ---------------- scratch (device globals; no allocs allowed) ----------------
__device__ __half   g_h0[NF];            // h_lin (x@W1, later h1@W2)  [fp16]
__device__ __half   g_h1[NF];            // h1 / h2                    [fp16]
__device__ float    g_dinv[N_NODES];     // rsqrt(1+deg)
__device__ int      g_degi[N_NODES];     // in-degree (excl self loop)
__device__ int      g_rowstart[N_NODES + 1];
__device__ int      g_cursor[N_NODES];
__device__ int      g_esrc[N_EDGES];     // CSR by dst: src ids
__device__ float    g_enorm[N_EDGES];    // CSR by dst: dinv[src]*dinv[dst]
__device__ float    g_cnt[N_GRAPHS];     // nodes per graph
__device__ float    g_psum[N_GRAPHS * F];
__device__ unsigned g_pmax[N_GRAPHS * F]; // float bits; valid since vals >= 0

// fp16 weights for both layers
__device__ __half g_W1[F * F], g_W2[F * F];

// ---------------- init ----------------
__global__ void k_init_small() {
    int i = blockIdx.x * blockDim.x + threadIdx.x;
    int stride = gridDim.x * blockDim.x;
    for (int j = i; j < N_NODES; j += stride) g_degi[j] = 0;
    for (int j = i; j < N_GRAPHS * F; j += stride) { g_psum[j] = 0.0f; g_pmax[j] = 0u; }
    for (int j = i; j < N_GRAPHS; j += stride) g_cnt[j] = 0.0f;
}

// ---------------- degree ----------------
__global__ void k_deg(const int* __restrict__ dst) {
    int e = blockIdx.x * blockDim.x + threadIdx.x;
    if (e < N_EDGES) atomicAdd(&g_degi[dst[e]], 1);
}

// ---------------- scan of degrees -> rowstart/cursor, fused dinv (1 block) ----------------
__global__ __launch_bounds__(1024) void k_scan() {
    __shared__ int part[1024];
    int t = threadIdx.x;
    const int CH = (N_NODES + 1023) / 1024;     // 49
    int s0 = t * CH;
    int s1 = min(s0 + CH, N_NODES);
    int sum = 0;
    for (int i = s0; i < s1; i++) {
        int d = g_degi[i];
        sum += d;
        g_dinv[i] = rsqrtf(1.0f + (float)d);    // self loop included
    }
    part[t] = sum;
    __syncthreads();
    for (int off = 1; off < 1024; off <<= 1) {
        int v = (t >= off) ? part[t - off] : 0;
        __syncthreads();
        part[t] += v;
        __syncthreads();
    }
    int excl = (t == 0) ? 0 : part[t - 1];
    for (int i = s0; i < s1; i++) {
        g_rowstart[i] = excl;
        g_cursor[i] = excl;
        excl += g_degi[i];
    }
    if (t == 1023) g_rowstart[N_NODES] = part[1023];   // grand total
}

// ---------------- CSR fill: place (src, norm) per edge, grouped by dst ----------------
__global__ void k_fill(const int* __restrict__ src, const int* __restrict__ dst) {
    int e = blockIdx.x * blockDim.x + threadIdx.x;
    if (e < N_EDGES) {
        int s = src[e], d = dst[e];
        int pos = atomicAdd(&g_cursor[d], 1);
        g_esrc[pos] = s;
        g_enorm[pos] = g_dinv[s] * g_dinv[d];
    }
}

// ---------------- weight convert: W1,W2 -> fp16 (one launch) ----------------
__global__ void k_convW(const float* __restrict__ W1, const float* __restrict__ W2) {
    int i = blockIdx.x * blockDim.x + threadIdx.x;
    if (i < F * F) {
        g_W1[i] = __float2half_rn(W1[i]);
        g_W2[i] = __float2half_rn(W2[i]);
    }
}

// ---------------- tensor-core GEMM: C[M,256] = A[M,256] @ W[256,256] ----------
// A fp16 (layer 1 converts fp32->fp16 at load), W fp16, fp32 accumulate, C fp16.
#define BM 128
#define BN 128
#define KC 32
#define APAD 40
#define BPAD 136

__device__ __forceinline__ void ldsm_x4(uint32_t& r0, uint32_t& r1, uint32_t& r2, uint32_t& r3,
                                        uint32_t addr) {
    asm volatile("ldmatrix.sync.aligned.m8n8.x4.shared.b16 {%0,%1,%2,%3}, [%4];\n"
                 : "=r"(r0), "=r"(r1), "=r"(r2), "=r"(r3) : "r"(addr));
}
__device__ __forceinline__ void ldsm_x4t(uint32_t& r0, uint32_t& r1, uint32_t& r2, uint32_t& r3,
                                         uint32_t addr) {
    asm volatile("ldmatrix.sync.aligned.m8n8.x4.trans.shared.b16 {%0,%1,%2,%3}, [%4];\n"
                 : "=r"(r0), "=r"(r1), "=r"(r2), "=r"(r3) : "r"(addr));
}
__device__ __forceinline__ void mma_fp16(float* c, const uint32_t* a, uint32_t b0, uint32_t b1) {
    asm volatile("mma.sync.aligned.m16n8k16.row.col.f32.f16.f16.f32 "
                 "{%0,%1,%2,%3}, {%4,%5,%6,%7}, {%8,%9}, {%0,%1,%2,%3};\n"
                 : "+f"(c[0]), "+f"(c[1]), "+f"(c[2]), "+f"(c[3])
                 : "r"(a[0]), "r"(a[1]), "r"(a[2]), "r"(a[3]), "r"(b0), "r"(b1));
}

template <bool HALF_A>
__global__ __launch_bounds__(256) void k_gemm_tc(const void* __restrict__ Aptr,
                                                 const __half* __restrict__ B,
                                                 __half* __restrict__ C, int M) {
    __shared__ __half sA[BM * APAD];
    __shared__ __half sB[KC * BPAD];

    const int tid  = threadIdx.x;
    const int lane = tid & 31;
    const int wid  = tid >> 5;
    const int wm   = wid >> 1;
    const int wn   = wid & 1;
    const int bm   = blockIdx.y * BM;
    const int bn   = blockIdx.x * BN;

    const int lr = lane & 7;
    const int lg = lane >> 3;
    const int rowoff = ((lg & 1) << 3) + lr;
    const int coloff = (lg & 2) << 2;

    float acc[2][8][4];
#pragma unroll
    for (int i = 0; i < 2; i++)
#pragma unroll
        for (int j = 0; j < 8; j++)
#pragma unroll
            for (int k = 0; k < 4; k++) acc[i][j][k] = 0.f;

    for (int kk = 0; kk < 256; kk += KC) {
        // ---- load A tile [BM x KC] fp16 into SMEM ----
#pragma unroll
        for (int i = 0; i < 4; i++) {
            int idx = i * 256 + tid;            // 0..1023 quad(4-half) slots
            int r = idx >> 3;                   // 0..127
            int c = (idx & 7) * 4;              // 0..28
            int grow = bm + r;
            uint32_t p0 = 0, p1 = 0;
            if (grow < M) {
                if (HALF_A) {
                    const __half* A = (const __half*)Aptr;
                    uint2 q = *(const uint2*)(A + (size_t)grow * 256 + kk + c);
                    p0 = q.x; p1 = q.y;
                } else {
                    const float* A = (const float*)Aptr;
                    float4 v = *(const float4*)(A + (size_t)grow * 256 + kk + c);
                    __half2 h0 = __floats2half2_rn(v.x, v.y);
                    __half2 h1 = __floats2half2_rn(v.z, v.w);
                    p0 = *(uint32_t*)&h0; p1 = *(uint32_t*)&h1;
                }
            }
            uint32_t* pa = (uint32_t*)&sA[r * APAD + c];
            pa[0] = p0; pa[1] = p1;
        }
        // ---- load B tile [KC x BN] fp16 ----
#pragma unroll
        for (int i = 0; i < 2; i++) {
            int idx = i * 256 + tid;
            int r = idx >> 4;
            int c = (idx & 15) * 8;
            uint4 vb = *(const uint4*)(B + (size_t)(kk + r) * 256 + bn + c);
            *(uint4*)&sB[r * BPAD + c] = vb;
        }
        __syncthreads();

#pragma unroll
        for (int kf = 0; kf < KC; kf += 16) {
            uint32_t ah[2][4];
#pragma unroll
            for (int mt = 0; mt < 2; mt++) {
                int rowi = (wm * 32 + mt * 16 + rowoff) * APAD + kf + coloff;
                ldsm_x4(ah[mt][0], ah[mt][1], ah[mt][2], ah[mt][3],
                        (uint32_t)__cvta_generic_to_shared(&sA[rowi]));
            }
            uint32_t bb[4][4];
#pragma unroll
            for (int nt4 = 0; nt4 < 4; nt4++) {
                int ci = (kf + rowoff) * BPAD + wn * 64 + nt4 * 16 + coloff;
                ldsm_x4t(bb[nt4][0], bb[nt4][1], bb[nt4][2], bb[nt4][3],
                         (uint32_t)__cvta_generic_to_shared(&sB[ci]));
            }
#pragma unroll
            for (int mt = 0; mt < 2; mt++) {
#pragma unroll
                for (int nt4 = 0; nt4 < 4; nt4++) {
                    mma_fp16(acc[mt][nt4 * 2 + 0], ah[mt], bb[nt4][0], bb[nt4][1]);
                    mma_fp16(acc[mt][nt4 * 2 + 1], ah[mt], bb[nt4][2], bb[nt4][3]);
                }
            }
        }
        __syncthreads();
    }

    // ---- store C as fp16 ----
    const int gid2 = lane >> 2;
    const int tig  = lane & 3;
#pragma unroll
    for (int mt = 0; mt < 2; mt++) {
#pragma unroll
        for (int nt = 0; nt < 8; nt++) {
            int row0 = bm + wm * 32 + mt * 16 + gid2;
            int col  = bn + wn * 64 + nt * 8 + tig * 2;
            __half* c0 = C + (size_t)row0 * 256 + col;
            if (row0 < M)
                *(__half2*)c0 = __floats2half2_rn(acc[mt][nt][0], acc[mt][nt][1]);
            if (row0 + 8 < M)
                *(__half2*)(c0 + 8 * 256) = __floats2half2_rn(acc[mt][nt][2], acc[mt][nt][3]);
        }
    }
}

// ---------------- CSR gather + self loop + bias + relu: one warp per dst node ----
__global__ __launch_bounds__(256) void k_gather(const __half* __restrict__ H,
                                                __half* __restrict__ OUT,
                                                const float* __restrict__ bias) {
    int node = blockIdx.x * 8 + (threadIdx.x >> 5);
    int lane = threadIdx.x & 31;
    if (node >= N_NODES) return;
    int e0 = g_rowstart[node];
    int e1 = g_rowstart[node + 1];
    const uint4* __restrict__ H16 = (const uint4*)H;   // 8 halfs per uint4, 32 per row

    float a[8];
#pragma unroll
    for (int i = 0; i < 8; i++) a[i] = 0.f;

#define ACC8(q, n)                                                        \
    do {                                                                  \
        __half2 p0 = *(__half2*)&(q).x, p1 = *(__half2*)&(q).y;           \
        __half2 p2 = *(__half2*)&(q).z, p3 = *(__half2*)&(q).w;           \
        float2 f0 = __half22float2(p0), f1 = __half22float2(p1);          \
        float2 f2 = __half22float2(p2), f3 = __half22float2(p3);          \
        a[0] = fmaf(n, f0.x, a[0]); a[1] = fmaf(n, f0.y, a[1]);           \
        a[2] = fmaf(n, f1.x, a[2]); a[3] = fmaf(n, f1.y, a[3]);           \
        a[4] = fmaf(n, f2.x, a[4]); a[5] = fmaf(n, f2.y, a[5]);           \
        a[6] = fmaf(n, f3.x, a[6]); a[7] = fmaf(n, f3.y, a[7]);           \
    } while (0)

    int e = e0;
    for (; e + 4 <= e1; e += 4) {
        int   s0 = g_esrc[e],  s1 = g_esrc[e + 1], s2 = g_esrc[e + 2], s3 = g_esrc[e + 3];
        float n0 = g_enorm[e], n1 = g_enorm[e + 1], n2 = g_enorm[e + 2], n3 = g_enorm[e + 3];
        uint4 q0 = H16[(size_t)s0 * 32 + lane];
        uint4 q1 = H16[(size_t)s1 * 32 + lane];
        uint4 q2 = H16[(size_t)s2 * 32 + lane];
        uint4 q3 = H16[(size_t)s3 * 32 + lane];
        ACC8(q0, n0); ACC8(q1, n1); ACC8(q2, n2); ACC8(q3, n3);
    }
    for (; e < e1; e++) {
        int   s0 = g_esrc[e];
        float n0 = g_enorm[e];
        uint4 q0 = H16[(size_t)s0 * 32 + lane];
        ACC8(q0, n0);
    }

    // self loop + bias + relu
    float di = g_dinv[node];
    float sl = di * di;
    uint4 qs = H16[(size_t)node * 32 + lane];
    ACC8(qs, sl);

    float4 b0 = ((const float4*)bias)[lane * 2];
    float4 b1 = ((const float4*)bias)[lane * 2 + 1];
    a[0] = fmaxf(a[0] + b0.x, 0.f); a[1] = fmaxf(a[1] + b0.y, 0.f);
    a[2] = fmaxf(a[2] + b0.z, 0.f); a[3] = fmaxf(a[3] + b0.w, 0.f);
    a[4] = fmaxf(a[4] + b1.x, 0.f); a[5] = fmaxf(a[5] + b1.y, 0.f);
    a[6] = fmaxf(a[6] + b1.z, 0.f); a[7] = fmaxf(a[7] + b1.w, 0.f);

    uint4 o;
    __half2 o0 = __floats2half2_rn(a[0], a[1]);
    __half2 o1 = __floats2half2_rn(a[2], a[3]);
    __half2 o2 = __floats2half2_rn(a[4], a[5]);
    __half2 o3 = __floats2half2_rn(a[6], a[7]);
    o.x = *(uint32_t*)&o0; o.y = *(uint32_t*)&o1;
    o.z = *(uint32_t*)&o2; o.w = *(uint32_t*)&o3;
    ((uint4*)OUT)[(size_t)node * 32 + lane] = o;
#undef ACC8
}

// ---------------- pooling over h2 + per-graph node counts ----------------
#define NPB 128
__global__ __launch_bounds__(256) void k_pool(const __half* __restrict__ H2,
                                              const int* __restrict__ batch) {
    int f  = threadIdx.x;
    int n0 = blockIdx.x * NPB;
    int n1 = min(n0 + NPB, N_NODES);
    int cur_g = batch[n0];
    float s = 0.f, m = 0.f;
    int cnt = 0;
    for (int n = n0; n < n1; ++n) {
        int g = batch[n];                       // uniform across block
        if (g != cur_g) {
            atomicAdd(&g_psum[cur_g * F + f], s);
            atomicMax(&g_pmax[cur_g * F + f], __float_as_uint(m));
            if (f == 0) atomicAdd(&g_cnt[cur_g], (float)cnt);
            s = 0.f; m = 0.f; cnt = 0; cur_g = g;
        }
        float v = __half2float(H2[(size_t)n * F + f]);
        s += v;
        m = fmaxf(m, v);
        cnt++;
    }
    atomicAdd(&g_psum[cur_g * F + f], s);
    atomicMax(&g_pmax[cur_g * F + f], __float_as_uint(m));
    if (f == 0) atomicAdd(&g_cnt[cur_g], (float)cnt);
}

// ---------------- final FC: out[64,128] = [mean|max|sum] @ Wfc + bfc ----------------
__global__ __launch_bounds__(128) void k_fc(const float* __restrict__ Wfc,
                                            const float* __restrict__ bfc,
                                            float* __restrict__ out) {
    int g = blockIdx.x;
    int j = threadIdx.x;
    float cinv = 1.f / fmaxf(g_cnt[g], 1.f);
    float acc = bfc[j];
#pragma unroll 4
    for (int k = 0; k < F; k++)
        acc = fmaf(g_psum[g * F + k] * cinv, Wfc[(size_t)k * F_OUT_ + j], acc);
#pragma unroll 4
    for (int k = 0; k < F; k++)
        acc = fmaf(__uint_as_float(g_pmax[g * F + k]), Wfc[(size_t)(F + k) * F_OUT_ + j], acc);
#pragma unroll 4
    for (int k = 0; k < F; k++)
        acc = fmaf(g_psum[g * F + k], Wfc[(size_t)(2 * F + k) * F_OUT_ + j], acc);
    out[(size_t)g * F_OUT_ + j] = acc;
}

// ---------------- launcher ----------------
extern "C" void kernel_launch(void* const* d_in, const int* in_sizes, int n_in,
                              void* d_out, int out_size) {
    const float* x     = (const float*)d_in[0];
    const int*   ei    = (const int*)d_in[1];
    const int*   batch = (const int*)d_in[2];
    int w = n_in - 6;
    const float* W1  = (const float*)d_in[w + 0];
    const float* b1  = (const float*)d_in[w + 1];
    const float* W2  = (const float*)d_in[w + 2];
    const float* b2  = (const float*)d_in[w + 3];
    const float* Wfc = (const float*)d_in[w + 4];
    const float* bfc = (const float*)d_in[w + 5];
    float* out = (float*)d_out;

    const int* src = ei;
    const int* dst = ei + N_EDGES;

    __half* h0; cudaGetSymbolAddress((void**)&h0, g_h0);
    __half* h1; cudaGetSymbolAddress((void**)&h1, g_h1);
    __half* W1d; cudaGetSymbolAddress((void**)&W1d, g_W1);
    __half* W2d; cudaGetSymbolAddress((void**)&W2d, g_W2);

    dim3 ggrid(2, (N_NODES + BM - 1) / BM);   // (2, 391)
    const int gather_blocks = (N_NODES + 7) / 8;

    k_init_small<<<256, 256>>>();
    k_convW<<<(F * F + 255) / 256, 256>>>(W1, W2);
    k_deg<<<(N_EDGES + 255) / 256, 256>>>(dst);
    k_scan<<<1, 1024>>>();
    k_fill<<<(N_EDGES + 255) / 256, 256>>>(src, dst);

    // layer 1
    k_gemm_tc<false><<<ggrid, 256>>>(x, W1d, h0, N_NODES);
    k_gather<<<gather_blocks, 256>>>(h0, h1, b1);           // h1 := relu(agg + b1)

    // layer 2
    k_gemm_tc<true><<<ggrid, 256>>>(h1, W2d, h0, N_NODES);
    k_gather<<<gather_blocks, 256>>>(h0, h1, b2);           // h1 := h2
    k_pool<<<(N_NODES + NPB - 1) / NPB, 256>>>(h1, batch);

    // readout
    k_fc<<<N_GRAPHS, 128>>>(Wfc, bfc, out);
    (void)in_sizes; (void)out_size;
}

// round 17
// speedup vs baseline: 5.1012x; 1.3310x over previous
#include <cuda_runtime.h>
#include <cuda_fp16.h>
#include <math.h>
#include <stdint.h>

// Problem constants (fixed by the dataset)
#define N_NODES   50000
#define N_EDGES   800000
#define N_GRAPHS  64
#define F         256      // F_IN == F_HID
#define F_OUT_    128
#define NF        (N_NODES * F)   // 12,800,000
#define NB_SCAN   196             // ceil(50000/256)

// ---------------- scratch (device globals; no allocs allowed) ----------------
__device__ __half   g_h0[NF];            // h_lin (x@W1, later h1@W2)  [fp16]
__device__ __half   g_h1[NF];            // h1 / h2                    [fp16]
__device__ float    g_dinv[N_NODES];     // rsqrt(1+deg)
__device__ int      g_degi[N_NODES];     // in-degree (excl self loop)
__device__ int      g_rowstart[N_NODES + 1];
__device__ int      g_cursor[N_NODES];
__device__ int      g_bsum[NB_SCAN];     // per-block degree sums
__device__ int      g_boff[NB_SCAN];     // exclusive block offsets
__device__ int      g_esrc[N_EDGES];     // CSR by dst: src ids
__device__ float    g_enorm[N_EDGES];    // CSR by dst: dinv[src]*dinv[dst]
__device__ float    g_cnt[N_GRAPHS];     // nodes per graph
__device__ float    g_psum[N_GRAPHS * F];
__device__ unsigned g_pmax[N_GRAPHS * F]; // float bits; valid since vals >= 0

// fp16 weights for both layers
__device__ __half g_W1[F * F], g_W2[F * F];

// ---------------- init ----------------
__global__ void k_init_small() {
    int i = blockIdx.x * blockDim.x + threadIdx.x;
    int stride = gridDim.x * blockDim.x;
    for (int j = i; j < N_NODES; j += stride) g_degi[j] = 0;
    for (int j = i; j < N_GRAPHS * F; j += stride) { g_psum[j] = 0.0f; g_pmax[j] = 0u; }
    for (int j = i; j < N_GRAPHS; j += stride) g_cnt[j] = 0.0f;
}

// ---------------- degree ----------------
__global__ void k_deg(const int* __restrict__ dst) {
    int e = blockIdx.x * blockDim.x + threadIdx.x;
    if (e < N_EDGES) atomicAdd(&g_degi[dst[e]], 1);
}

// ---------------- phase A: per-block degree sums + fused dinv ----------------
__global__ __launch_bounds__(256) void k_part() {
    __shared__ int sh[256];
    int t = threadIdx.x;
    int i = blockIdx.x * 256 + t;
    int d = 0;
    if (i < N_NODES) {
        d = g_degi[i];
        g_dinv[i] = rsqrtf(1.0f + (float)d);    // self loop included
    }
    sh[t] = d;
    __syncthreads();
#pragma unroll
    for (int off = 128; off > 0; off >>= 1) {
        if (t < off) sh[t] += sh[t + off];
        __syncthreads();
    }
    if (t == 0) g_bsum[blockIdx.x] = sh[0];
}

// ---------------- phase B: scan of block sums (1 small block) ----------------
__global__ __launch_bounds__(256) void k_scan_small() {
    __shared__ int sh[256];
    int t = threadIdx.x;
    int v = (t < NB_SCAN) ? g_bsum[t] : 0;
    sh[t] = v;
    __syncthreads();
#pragma unroll
    for (int off = 1; off < 256; off <<= 1) {
        int x = (t >= off) ? sh[t - off] : 0;
        __syncthreads();
        sh[t] += x;
        __syncthreads();
    }
    if (t < NB_SCAN) g_boff[t] = sh[t] - v;     // exclusive
    if (t == 255) g_rowstart[N_NODES] = sh[255]; // grand total
}

// ---------------- phase C: per-block exclusive scan -> rowstart/cursor ------
__global__ __launch_bounds__(256) void k_rows() {
    __shared__ int sh[256];
    int t = threadIdx.x;
    int i = blockIdx.x * 256 + t;
    int v = (i < N_NODES) ? g_degi[i] : 0;
    sh[t] = v;
    __syncthreads();
#pragma unroll
    for (int off = 1; off < 256; off <<= 1) {
        int x = (t >= off) ? sh[t - off] : 0;
        __syncthreads();
        sh[t] += x;
        __syncthreads();
    }
    if (i < N_NODES) {
        int pos = g_boff[blockIdx.x] + sh[t] - v;   // exclusive
        g_rowstart[i] = pos;
        g_cursor[i] = pos;
    }
}

// ---------------- CSR fill: place (src, norm) per edge, grouped by dst ----------------
__global__ void k_fill(const int* __restrict__ src, const int* __restrict__ dst) {
    int e = blockIdx.x * blockDim.x + threadIdx.x;
    if (e < N_EDGES) {
        int s = src[e], d = dst[e];
        int pos = atomicAdd(&g_cursor[d], 1);
        g_esrc[pos] = s;
        g_enorm[pos] = g_dinv[s] * g_dinv[d];
    }
}

// ---------------- weight convert: W1,W2 -> fp16 (one launch) ----------------
__global__ void k_convW(const float* __restrict__ W1, const float* __restrict__ W2) {
    int i = blockIdx.x * blockDim.x + threadIdx.x;
    if (i < F * F) {
        g_W1[i] = __float2half_rn(W1[i]);
        g_W2[i] = __float2half_rn(W2[i]);
    }
}

// ---------------- tensor-core GEMM: C[M,256] = A[M,256] @ W[256,256] ----------
// A fp16 (layer 1 converts fp32->fp16 at load), W fp16, fp32 accumulate, C fp16.
#define BM 128
#define BN 128
#define KC 32
#define APAD 40
#define BPAD 136

__device__ __forceinline__ void ldsm_x4(uint32_t& r0, uint32_t& r1, uint32_t& r2, uint32_t& r3,
                                        uint32_t addr) {
    asm volatile("ldmatrix.sync.aligned.m8n8.x4.shared.b16 {%0,%1,%2,%3}, [%4];\n"
                 : "=r"(r0), "=r"(r1), "=r"(r2), "=r"(r3) : "r"(addr));
}
__device__ __forceinline__ void ldsm_x4t(uint32_t& r0, uint32_t& r1, uint32_t& r2, uint32_t& r3,
                                         uint32_t addr) {
    asm volatile("ldmatrix.sync.aligned.m8n8.x4.trans.shared.b16 {%0,%1,%2,%3}, [%4];\n"
                 : "=r"(r0), "=r"(r1), "=r"(r2), "=r"(r3) : "r"(addr));
}
__device__ __forceinline__ void mma_fp16(float* c, const uint32_t* a, uint32_t b0, uint32_t b1) {
    asm volatile("mma.sync.aligned.m16n8k16.row.col.f32.f16.f16.f32 "
                 "{%0,%1,%2,%3}, {%4,%5,%6,%7}, {%8,%9}, {%0,%1,%2,%3};\n"
                 : "+f"(c[0]), "+f"(c[1]), "+f"(c[2]), "+f"(c[3])
                 : "r"(a[0]), "r"(a[1]), "r"(a[2]), "r"(a[3]), "r"(b0), "r"(b1));
}

template <bool HALF_A>
__global__ __launch_bounds__(256) void k_gemm_tc(const void* __restrict__ Aptr,
                                                 const __half* __restrict__ B,
                                                 __half* __restrict__ C, int M) {
    __shared__ __half sA[BM * APAD];
    __shared__ __half sB[KC * BPAD];

    const int tid  = threadIdx.x;
    const int lane = tid & 31;
    const int wid  = tid >> 5;
    const int wm   = wid >> 1;
    const int wn   = wid & 1;
    const int bm   = blockIdx.y * BM;
    const int bn   = blockIdx.x * BN;

    const int lr = lane & 7;
    const int lg = lane >> 3;
    const int rowoff = ((lg & 1) << 3) + lr;
    const int coloff = (lg & 2) << 2;

    float acc[2][8][4];
#pragma unroll
    for (int i = 0; i < 2; i++)
#pragma unroll
        for (int j = 0; j < 8; j++)
#pragma unroll
            for (int k = 0; k < 4; k++) acc[i][j][k] = 0.f;

    for (int kk = 0; kk < 256; kk += KC) {
        // ---- load A tile [BM x KC] fp16 into SMEM ----
#pragma unroll
        for (int i = 0; i < 4; i++) {
            int idx = i * 256 + tid;            // 0..1023 quad(4-half) slots
            int r = idx >> 3;                   // 0..127
            int c = (idx & 7) * 4;              // 0..28
            int grow = bm + r;
            uint32_t p0 = 0, p1 = 0;
            if (grow < M) {
                if (HALF_A) {
                    const __half* A = (const __half*)Aptr;
                    uint2 q = *(const uint2*)(A + (size_t)grow * 256 + kk + c);
                    p0 = q.x; p1 = q.y;
                } else {
                    const float* A = (const float*)Aptr;
                    float4 v = *(const float4*)(A + (size_t)grow * 256 + kk + c);
                    __half2 h0 = __floats2half2_rn(v.x, v.y);
                    __half2 h1 = __floats2half2_rn(v.z, v.w);
                    p0 = *(uint32_t*)&h0; p1 = *(uint32_t*)&h1;
                }
            }
            uint32_t* pa = (uint32_t*)&sA[r * APAD + c];
            pa[0] = p0; pa[1] = p1;
        }
        // ---- load B tile [KC x BN] fp16 ----
#pragma unroll
        for (int i = 0; i < 2; i++) {
            int idx = i * 256 + tid;
            int r = idx >> 4;
            int c = (idx & 15) * 8;
            uint4 vb = *(const uint4*)(B + (size_t)(kk + r) * 256 + bn + c);
            *(uint4*)&sB[r * BPAD + c] = vb;
        }
        __syncthreads();

#pragma unroll
        for (int kf = 0; kf < KC; kf += 16) {
            uint32_t ah[2][4];
#pragma unroll
            for (int mt = 0; mt < 2; mt++) {
                int rowi = (wm * 32 + mt * 16 + rowoff) * APAD + kf + coloff;
                ldsm_x4(ah[mt][0], ah[mt][1], ah[mt][2], ah[mt][3],
                        (uint32_t)__cvta_generic_to_shared(&sA[rowi]));
            }
            uint32_t bb[4][4];
#pragma unroll
            for (int nt4 = 0; nt4 < 4; nt4++) {
                int ci = (kf + rowoff) * BPAD + wn * 64 + nt4 * 16 + coloff;
                ldsm_x4t(bb[nt4][0], bb[nt4][1], bb[nt4][2], bb[nt4][3],
                         (uint32_t)__cvta_generic_to_shared(&sB[ci]));
            }
#pragma unroll
            for (int mt = 0; mt < 2; mt++) {
#pragma unroll
                for (int nt4 = 0; nt4 < 4; nt4++) {
                    mma_fp16(acc[mt][nt4 * 2 + 0], ah[mt], bb[nt4][0], bb[nt4][1]);
                    mma_fp16(acc[mt][nt4 * 2 + 1], ah[mt], bb[nt4][2], bb[nt4][3]);
                }
            }
        }
        __syncthreads();
    }

    // ---- store C as fp16 ----
    const int gid2 = lane >> 2;
    const int tig  = lane & 3;
#pragma unroll
    for (int mt = 0; mt < 2; mt++) {
#pragma unroll
        for (int nt = 0; nt < 8; nt++) {
            int row0 = bm + wm * 32 + mt * 16 + gid2;
            int col  = bn + wn * 64 + nt * 8 + tig * 2;
            __half* c0 = C + (size_t)row0 * 256 + col;
            if (row0 < M)
                *(__half2*)c0 = __floats2half2_rn(acc[mt][nt][0], acc[mt][nt][1]);
            if (row0 + 8 < M)
                *(__half2*)(c0 + 8 * 256) = __floats2half2_rn(acc[mt][nt][2], acc[mt][nt][3]);
        }
    }
}

// ---------------- CSR gather + self loop + bias + relu: one warp per dst node ----
__global__ __launch_bounds__(256) void k_gather(const __half* __restrict__ H,
                                                __half* __restrict__ OUT,
                                                const float* __restrict__ bias) {
    int node = blockIdx.x * 8 + (threadIdx.x >> 5);
    int lane = threadIdx.x & 31;
    if (node >= N_NODES) return;
    int e0 = g_rowstart[node];
    int e1 = g_rowstart[node + 1];
    const uint4* __restrict__ H16 = (const uint4*)H;   // 8 halfs per uint4, 32 per row

    float a[8];
#pragma unroll
    for (int i = 0; i < 8; i++) a[i] = 0.f;

#define ACC8(q, n)                                                        \
    do {                                                                  \
        __half2 p0 = *(__half2*)&(q).x, p1 = *(__half2*)&(q).y;           \
        __half2 p2 = *(__half2*)&(q).z, p3 = *(__half2*)&(q).w;           \
        float2 f0 = __half22float2(p0), f1 = __half22float2(p1);          \
        float2 f2 = __half22float2(p2), f3 = __half22float2(p3);          \
        a[0] = fmaf(n, f0.x, a[0]); a[1] = fmaf(n, f0.y, a[1]);           \
        a[2] = fmaf(n, f1.x, a[2]); a[3] = fmaf(n, f1.y, a[3]);           \
        a[4] = fmaf(n, f2.x, a[4]); a[5] = fmaf(n, f2.y, a[5]);           \
        a[6] = fmaf(n, f3.x, a[6]); a[7] = fmaf(n, f3.y, a[7]);           \
    } while (0)

    int e = e0;
    for (; e + 4 <= e1; e += 4) {
        int   s0 = g_esrc[e],  s1 = g_esrc[e + 1], s2 = g_esrc[e + 2], s3 = g_esrc[e + 3];
        float n0 = g_enorm[e], n1 = g_enorm[e + 1], n2 = g_enorm[e + 2], n3 = g_enorm[e + 3];
        uint4 q0 = H16[(size_t)s0 * 32 + lane];
        uint4 q1 = H16[(size_t)s1 * 32 + lane];
        uint4 q2 = H16[(size_t)s2 * 32 + lane];
        uint4 q3 = H16[(size_t)s3 * 32 + lane];
        ACC8(q0, n0); ACC8(q1, n1); ACC8(q2, n2); ACC8(q3, n3);
    }
    for (; e < e1; e++) {
        int   s0 = g_esrc[e];
        float n0 = g_enorm[e];
        uint4 q0 = H16[(size_t)s0 * 32 + lane];
        ACC8(q0, n0);
    }

    // self loop + bias + relu
    float di = g_dinv[node];
    float sl = di * di;
    uint4 qs = H16[(size_t)node * 32 + lane];
    ACC8(qs, sl);

    float4 b0 = ((const float4*)bias)[lane * 2];
    float4 b1 = ((const float4*)bias)[lane * 2 + 1];
    a[0] = fmaxf(a[0] + b0.x, 0.f); a[1] = fmaxf(a[1] + b0.y, 0.f);
    a[2] = fmaxf(a[2] + b0.z, 0.f); a[3] = fmaxf(a[3] + b0.w, 0.f);
    a[4] = fmaxf(a[4] + b1.x, 0.f); a[5] = fmaxf(a[5] + b1.y, 0.f);
    a[6] = fmaxf(a[6] + b1.z, 0.f); a[7] = fmaxf(a[7] + b1.w, 0.f);

    uint4 o;
    __half2 o0 = __floats2half2_rn(a[0], a[1]);
    __half2 o1 = __floats2half2_rn(a[2], a[3]);
    __half2 o2 = __floats2half2_rn(a[4], a[5]);
    __half2 o3 = __floats2half2_rn(a[6], a[7]);
    o.x = *(uint32_t*)&o0; o.y = *(uint32_t*)&o1;
    o.z = *(uint32_t*)&o2; o.w = *(uint32_t*)&o3;
    ((uint4*)OUT)[(size_t)node * 32 + lane] = o;
#undef ACC8
}

// ---------------- pooling over h2 + per-graph node counts ----------------
#define NPB 128
__global__ __launch_bounds__(256) void k_pool(const __half* __restrict__ H2,
                                              const int* __restrict__ batch) {
    int f  = threadIdx.x;
    int n0 = blockIdx.x * NPB;
    int n1 = min(n0 + NPB, N_NODES);
    int cur_g = batch[n0];
    float s = 0.f, m = 0.f;
    int cnt = 0;
    for (int n = n0; n < n1; ++n) {
        int g = batch[n];                       // uniform across block
        if (g != cur_g) {
            atomicAdd(&g_psum[cur_g * F + f], s);
            atomicMax(&g_pmax[cur_g * F + f], __float_as_uint(m));
            if (f == 0) atomicAdd(&g_cnt[cur_g], (float)cnt);
            s = 0.f; m = 0.f; cnt = 0; cur_g = g;
        }
        float v = __half2float(H2[(size_t)n * F + f]);
        s += v;
        m = fmaxf(m, v);
        cnt++;
    }
    atomicAdd(&g_psum[cur_g * F + f], s);
    atomicMax(&g_pmax[cur_g * F + f], __float_as_uint(m));
    if (f == 0) atomicAdd(&g_cnt[cur_g], (float)cnt);
}

// ---------------- final FC: out[64,128] = [mean|max|sum] @ Wfc + bfc ----------------
__global__ __launch_bounds__(128) void k_fc(const float* __restrict__ Wfc,
                                            const float* __restrict__ bfc,
                                            float* __restrict__ out) {
    int g = blockIdx.x;
    int j = threadIdx.x;
    float cinv = 1.f / fmaxf(g_cnt[g], 1.f);
    float acc = bfc[j];
#pragma unroll 4
    for (int k = 0; k < F; k++)
        acc = fmaf(g_psum[g * F + k] * cinv, Wfc[(size_t)k * F_OUT_ + j], acc);
#pragma unroll 4
    for (int k = 0; k < F; k++)
        acc = fmaf(__uint_as_float(g_pmax[g * F + k]), Wfc[(size_t)(F + k) * F_OUT_ + j], acc);
#pragma unroll 4
    for (int k = 0; k < F; k++)
        acc = fmaf(g_psum[g * F + k], Wfc[(size_t)(2 * F + k) * F_OUT_ + j], acc);
    out[(size_t)g * F_OUT_ + j] = acc;
}

// ---------------- launcher ----------------
extern "C" void kernel_launch(void* const* d_in, const int* in_sizes, int n_in,
                              void* d_out, int out_size) {
    const float* x     = (const float*)d_in[0];
    const int*   ei    = (const int*)d_in[1];
    const int*   batch = (const int*)d_in[2];
    int w = n_in - 6;
    const float* W1  = (const float*)d_in[w + 0];
    const float* b1  = (const float*)d_in[w + 1];
    const float* W2  = (const float*)d_in[w + 2];
    const float* b2  = (const float*)d_in[w + 3];
    const float* Wfc = (const float*)d_in[w + 4];
    const float* bfc = (const float*)d_in[w + 5];
    float* out = (float*)d_out;

    const int* src = ei;
    const int* dst = ei + N_EDGES;

    __half* h0; cudaGetSymbolAddress((void**)&h0, g_h0);
    __half* h1; cudaGetSymbolAddress((void**)&h1, g_h1);
    __half* W1d; cudaGetSymbolAddress((void**)&W1d, g_W1);
    __half* W2d; cudaGetSymbolAddress((void**)&W2d, g_W2);

    dim3 ggrid(2, (N_NODES + BM - 1) / BM);   // (2, 391)
    const int gather_blocks = (N_NODES + 7) / 8;

    k_init_small<<<256, 256>>>();
    k_convW<<<(F * F + 255) / 256, 256>>>(W1, W2);
    k_deg<<<(N_EDGES + 255) / 256, 256>>>(dst);
    k_part<<<NB_SCAN, 256>>>();
    k_scan_small<<<1, 256>>>();
    k_rows<<<NB_SCAN, 256>>>();
    k_fill<<<(N_EDGES + 255) / 256, 256>>>(src, dst);

    // layer 1
    k_gemm_tc<false><<<ggrid, 256>>>(x, W1d, h0, N_NODES);
    k_gather<<<gather_blocks, 256>>>(h0, h1, b1);           // h1 := relu(agg + b1)

    // layer 2
    k_gemm_tc<true><<<ggrid, 256>>>(h1, W2d, h0, N_NODES);
    k_gather<<<gather_blocks, 256>>>(h0, h1, b2);           // h1 := h2
    k_pool<<<(N_NODES + NPB - 1) / NPB, 256>>>(h1, batch);

    // readout
    k_fc<<<N_GRAPHS, 128>>>(Wfc, bfc, out);
    (void)in_sizes; (void)out_size;
}